// round 1
// baseline (speedup 1.0000x reference)
#include <cuda_runtime.h>

// ---------------------------------------------------------------------------
// Problem constants
// ---------------------------------------------------------------------------
#define HH   8
#define DD   128
#define KDD  16
#define EE   128
#define BB   16
#define GG   501
#define NPP  250
#define NTOK (BB*GG)      // 8016
#define NHALF (BB*NPP)    // 4000
#define KR   20           // padded smem row (16 data + 4 pad floats) -> conflict-free LDS.128
// norm * log2(e) : softmax computed in base-2
#define SCALE2 0.3606737602222409f

// ---------------------------------------------------------------------------
// Scratch (static __device__ arrays: allocation-free per harness rules)
// ---------------------------------------------------------------------------
__device__ float g_Q[HH*NTOK*KDD];
__device__ float g_K[HH*NTOK*KDD];
__device__ float g_V[HH*NTOK*KDD];
// order: [0]=W1(Q_pick single) [1]=W2(Q_pick_ap vs K_pick) [2]=W3(Q_pick_ad vs K_del)
//        [3]=W4(Q_del single)  [4]=W5(Q_del_ad vs K_del)   [5]=W6(Q_del_ap vs K_pick)
__device__ float g_EQ[6][HH*NHALF*KDD];
__device__ float g_heads[HH*NTOK*KDD];

struct WArgs { const float* w[9]; };

// ---------------------------------------------------------------------------
// Kernel 1: projections.  out[h, row, k] = sum_d q[row, d] * W[h, d, k]
// grid (rowTiles=126, H=8, job=9), block 64 threads.
// jobs 0..2: full range (Q,K,V).  jobs 3..5: pick tokens (off=1).
// jobs 6..8: delivery tokens (off=251).
// ---------------------------------------------------------------------------
__global__ void proj_kernel(const float* __restrict__ q, WArgs a) {
    const int job  = blockIdx.z;
    const int h    = blockIdx.y;
    const int tile = blockIdx.x;
    const bool full = (job < 3);
    const int nrows = full ? NTOK : NHALF;
    const int r0 = tile * 64;
    if (r0 >= nrows) return;

    __shared__ float qs[64*129];   // padded stride 129: conflict-free
    __shared__ float ws[DD*KDD];   // 128 x 16

    const float* W = a.w[job] + (size_t)h * DD * KDD;
    const int tid = threadIdx.x;

    for (int i = tid; i < DD*KDD; i += 64) ws[i] = W[i];

    const int off = full ? 0 : ((job < 6) ? 1 : (NPP + 1));
    for (int i = tid; i < 64*DD; i += 64) {
        int lr = i >> 7, d = i & 127;
        int rt = r0 + lr;
        float v = 0.f;
        if (rt < nrows) {
            size_t src;
            if (full) src = (size_t)rt * DD + d;
            else {
                int b = rt / NPP, p = rt % NPP;
                src = ((size_t)(b*GG + off + p)) * DD + d;
            }
            v = q[src];
        }
        qs[lr*129 + d] = v;
    }
    __syncthreads();

    const int cg = tid & 3;          // 4 col-groups of 4 cols
    const int rg = tid >> 2;         // 16 row-groups of 4 rows
    float acc[4][4];
#pragma unroll
    for (int i = 0; i < 4; i++)
#pragma unroll
        for (int j = 0; j < 4; j++) acc[i][j] = 0.f;

    const float* qrow = qs + (rg*4)*129;
    const int c0 = cg*4;
#pragma unroll 8
    for (int d = 0; d < DD; d++) {
        float w0 = ws[d*KDD + c0 + 0];
        float w1 = ws[d*KDD + c0 + 1];
        float w2 = ws[d*KDD + c0 + 2];
        float w3 = ws[d*KDD + c0 + 3];
#pragma unroll
        for (int ri = 0; ri < 4; ri++) {
            float qv = qrow[ri*129 + d];
            acc[ri][0] += qv*w0; acc[ri][1] += qv*w1;
            acc[ri][2] += qv*w2; acc[ri][3] += qv*w3;
        }
    }

    float* outp;
    if      (job == 0) outp = g_Q;
    else if (job == 1) outp = g_K;
    else if (job == 2) outp = g_V;
    else               outp = g_EQ[job-3];

#pragma unroll
    for (int ri = 0; ri < 4; ri++) {
        int rt = r0 + rg*4 + ri;
        if (rt < nrows) {
            float* o = outp + ((size_t)h*nrows + rt)*KDD + c0;
            o[0] = acc[ri][0]; o[1] = acc[ri][1];
            o[2] = acc[ri][2]; o[3] = acc[ri][3];
        }
    }
}

// ---------------------------------------------------------------------------
// Attention helpers
// ---------------------------------------------------------------------------
__device__ __forceinline__ float dot16v(const float* q,
        const float4 k0, const float4 k1, const float4 k2, const float4 k3) {
    float a = q[0]*k0.x + q[1]*k0.y + q[2]*k0.z + q[3]*k0.w;
    float b = q[4]*k1.x + q[5]*k1.y + q[6]*k1.z + q[7]*k1.w;
    float c = q[8]*k2.x + q[9]*k2.y + q[10]*k2.z + q[11]*k2.w;
    float d = q[12]*k3.x + q[13]*k3.y + q[14]*k3.z + q[15]*k3.w;
    return (a + b) + (c + d);
}

__device__ __forceinline__ void softupd(float s2,
        const float4 v0, const float4 v1, const float4 v2, const float4 v3,
        float& m, float& l, float* acc) {
    if (s2 > m) {                      // rare rescale path
        float c = exp2f(m - s2);       // m = -1e30 initially -> c = 0 (no NaN)
        l *= c;
#pragma unroll
        for (int k = 0; k < 16; k++) acc[k] *= c;
        m = s2;
    }
    float w = exp2f(s2 - m);           // masked entries (s2 = -1e30) -> w = 0
    l += w;
    acc[0]  += w*v0.x; acc[1]  += w*v0.y; acc[2]  += w*v0.z; acc[3]  += w*v0.w;
    acc[4]  += w*v1.x; acc[5]  += w*v1.y; acc[6]  += w*v1.z; acc[7]  += w*v1.w;
    acc[8]  += w*v2.x; acc[9]  += w*v2.y; acc[10] += w*v2.z; acc[11] += w*v2.w;
    acc[12] += w*v3.x; acc[13] += w*v3.y; acc[14] += w*v3.z; acc[15] += w*v3.w;
}

// ---------------------------------------------------------------------------
// Kernel 2: fused attention (scores + softmax + AV) per (h,b).
// grid (H*B=128, 8 query-tiles of 64), block 256 (8 warps).
// Each warp handles groups of 4 queries; K/V tile in padded smem.
// ---------------------------------------------------------------------------
__global__ void __launch_bounds__(256, 1) attn_kernel() {
    extern __shared__ float sm[];
    float* Ks = sm;                 // GG * KR floats
    float* Vs = sm + GG*KR;

    const int hb   = blockIdx.x;    // h*B + b
    const int tid  = threadIdx.x;
    const int lane = tid & 31;
    const int warp = tid >> 5;

    {   // load K and V tiles (float4, conflict-free-ish)
        const float4* K4 = (const float4*)(g_K + (size_t)hb * GG * KDD);
        const float4* V4 = (const float4*)(g_V + (size_t)hb * GG * KDD);
        float4* Ks4 = (float4*)Ks;
        float4* Vs4 = (float4*)Vs;
        for (int i = tid; i < GG*4; i += 256) {
            int j = i >> 2, k4 = i & 3;
            Ks4[j*5 + k4] = K4[i];
            Vs4[j*5 + k4] = V4[i];
        }
    }
    __syncthreads();

    const int qbase = blockIdx.y * 64;

    for (int gi = warp; gi < 16; gi += 8) {
        const int n0 = qbase + gi*4;
        if (n0 >= GG) continue;

        float m[4], l[4], acc[4][16], qv[4][16];
        bool valid[4];
#pragma unroll
        for (int i = 0; i < 4; i++) {
            int n = n0 + i;
            valid[i] = (n < GG);
            m[i] = -1e30f; l[i] = 0.f;
            const float* qp = g_Q + ((size_t)hb*GG + (valid[i] ? n : 0))*KDD;
#pragma unroll
            for (int k = 0; k < 16; k++) {
                acc[i][k] = 0.f;
                qv[i][k] = valid[i] ? qp[k] : 0.f;
            }
        }

        // ---- base: all G keys ----
        for (int j = lane; j < GG; j += 32) {
            const float4* kr = (const float4*)(Ks + j*KR);
            const float4* vr = (const float4*)(Vs + j*KR);
            float4 k0 = kr[0], k1 = kr[1], k2 = kr[2], k3 = kr[3];
            float4 v0 = vr[0], v1 = vr[1], v2 = vr[2], v3 = vr[3];
#pragma unroll
            for (int i = 0; i < 4; i++) {
                float s2 = dot16v(qv[i], k0,k1,k2,k3) * SCALE2;
                softupd(s2, v0,v1,v2,v3, m[i], l[i], acc[i]);
            }
        }

        // ---- query classification ----
        bool pk[4], dl[4];
#pragma unroll
        for (int i = 0; i < 4; i++) {
            int n = n0 + i;
            pk[i] = (n >= 1) && (n <= NPP);
            dl[i] = (n >= NPP+1) && (n < GG);
        }

        // ---- extras phase A: keys 1..NPP (pick keys) ----
        // pick query uses W2 (EQ1), delivery query uses W6 (EQ5)
#pragma unroll
        for (int i = 0; i < 4; i++) {
            int n = n0 + i;
            if (pk[i] || dl[i]) {
                int p = pk[i] ? (n-1) : (n-NPP-1);
                const float* src = (pk[i] ? g_EQ[1] : g_EQ[5]) + ((size_t)hb*NPP + p)*KDD;
#pragma unroll
                for (int k = 0; k < 16; k++) qv[i][k] = src[k];
            }
        }
        for (int j = lane; j < NPP; j += 32) {
            const int key = 1 + j;
            const float4* kr = (const float4*)(Ks + key*KR);
            const float4* vr = (const float4*)(Vs + key*KR);
            float4 k0 = kr[0], k1 = kr[1], k2 = kr[2], k3 = kr[3];
            float4 v0 = vr[0], v1 = vr[1], v2 = vr[2], v3 = vr[3];
#pragma unroll
            for (int i = 0; i < 4; i++) {
                float s2 = dot16v(qv[i], k0,k1,k2,k3) * SCALE2;
                if (!(pk[i] || dl[i])) s2 = -1e30f;   // query 0 / OOB: no contribution
                softupd(s2, v0,v1,v2,v3, m[i], l[i], acc[i]);
            }
        }

        // ---- extras phase B: keys NPP+1..2*NPP (delivery keys) ----
        // pick query uses W3 (EQ2), delivery query uses W5 (EQ4)
#pragma unroll
        for (int i = 0; i < 4; i++) {
            int n = n0 + i;
            if (pk[i] || dl[i]) {
                int p = pk[i] ? (n-1) : (n-NPP-1);
                const float* src = (pk[i] ? g_EQ[2] : g_EQ[4]) + ((size_t)hb*NPP + p)*KDD;
#pragma unroll
                for (int k = 0; k < 16; k++) qv[i][k] = src[k];
            }
        }
        for (int j = lane; j < NPP; j += 32) {
            const int key = NPP + 1 + j;
            const float4* kr = (const float4*)(Ks + key*KR);
            const float4* vr = (const float4*)(Vs + key*KR);
            float4 k0 = kr[0], k1 = kr[1], k2 = kr[2], k3 = kr[3];
            float4 v0 = vr[0], v1 = vr[1], v2 = vr[2], v3 = vr[3];
#pragma unroll
            for (int i = 0; i < 4; i++) {
                float s2 = dot16v(qv[i], k0,k1,k2,k3) * SCALE2;
                if (!(pk[i] || dl[i])) s2 = -1e30f;
                softupd(s2, v0,v1,v2,v3, m[i], l[i], acc[i]);
            }
        }

        // ---- single paired extras: pick q -> K_del[p] (W1=EQ0),
        //      delivery q -> K_pick[p] (W4=EQ3). lane==i handles query i
        //      (constant register indices; contributions merge in reduction) ----
#pragma unroll
        for (int i = 0; i < 4; i++) {
            if (lane == i) {
                int n = n0 + i;
                if (pk[i] || dl[i]) {
                    int p   = pk[i] ? (n-1) : (n-NPP-1);
                    int key = pk[i] ? (NPP+1+p) : (1+p);
                    const float* sq = (pk[i] ? g_EQ[0] : g_EQ[3]) + ((size_t)hb*NPP + p)*KDD;
                    float qq[16];
#pragma unroll
                    for (int k = 0; k < 16; k++) qq[k] = sq[k];
                    const float4* kr = (const float4*)(Ks + key*KR);
                    const float4* vr = (const float4*)(Vs + key*KR);
                    float s2 = dot16v(qq, kr[0],kr[1],kr[2],kr[3]) * SCALE2;
                    softupd(s2, vr[0],vr[1],vr[2],vr[3], m[i], l[i], acc[i]);
                }
            }
        }

        // ---- warp reduction + store ----
#pragma unroll
        for (int i = 0; i < 4; i++) {
            float M = m[i];
#pragma unroll
            for (int o = 16; o > 0; o >>= 1)
                M = fmaxf(M, __shfl_xor_sync(0xffffffffu, M, o));
            float c = exp2f(m[i] - M);
            float li = l[i] * c;
#pragma unroll
            for (int o = 16; o > 0; o >>= 1)
                li += __shfl_xor_sync(0xffffffffu, li, o);
#pragma unroll
            for (int k = 0; k < 16; k++) {
                float a = acc[i][k] * c;
#pragma unroll
                for (int o = 16; o > 0; o >>= 1)
                    a += __shfl_xor_sync(0xffffffffu, a, o);
                acc[i][k] = a;
            }
            if (lane == 0 && valid[i]) {
                float inv = 1.0f / li;
                float* o = g_heads + ((size_t)hb*GG + n0 + i)*KDD;
#pragma unroll
                for (int k = 0; k < 16; k++) o[k] = acc[i][k] * inv;
            }
        }
    }
}

// ---------------------------------------------------------------------------
// Kernel 3: output projection. out[t, e] = sum_{hk} heads[t, hk] * Wout[hk, e]
// grid 251 (32 tokens each), block 128 (16 e-groups x 8 t-groups), 4x8 tile.
// ---------------------------------------------------------------------------
__global__ void out_kernel(const float* __restrict__ Wout, float* __restrict__ out) {
    extern __shared__ float sm[];
    float* hs = sm;                  // 32 * 129 (padded)
    float* ws = sm + 32*129;         // 128 * 128

    const int tid = threadIdx.x;
    const int t0  = blockIdx.x * 32;

    for (int i = tid; i < HH*KDD*EE; i += 128) ws[i] = Wout[i];
    for (int i = tid; i < 32*HH*KDD; i += 128) {
        int t = i >> 7, hk = i & 127;
        int tt = t0 + t;
        float v = 0.f;
        if (tt < NTOK)
            v = g_heads[((size_t)(hk >> 4)*NTOK + tt)*KDD + (hk & 15)];
        hs[t*129 + hk] = v;
    }
    __syncthreads();

    const int eg = tid & 15;         // e = eg + 16*ei, ei=0..7
    const int tg = tid >> 4;         // 8 groups of 4 tokens
    float acc[4][8];
#pragma unroll
    for (int ti = 0; ti < 4; ti++)
#pragma unroll
        for (int ei = 0; ei < 8; ei++) acc[ti][ei] = 0.f;

#pragma unroll 4
    for (int hk = 0; hk < 128; hk++) {
        float w[8], hv[4];
#pragma unroll
        for (int ei = 0; ei < 8; ei++) w[ei] = ws[hk*128 + eg + 16*ei];
#pragma unroll
        for (int ti = 0; ti < 4; ti++) hv[ti] = hs[(tg*4 + ti)*129 + hk];
#pragma unroll
        for (int ti = 0; ti < 4; ti++)
#pragma unroll
            for (int ei = 0; ei < 8; ei++) acc[ti][ei] += hv[ti]*w[ei];
    }

#pragma unroll
    for (int ti = 0; ti < 4; ti++) {
        int tt = t0 + tg*4 + ti;
        if (tt < NTOK) {
#pragma unroll
            for (int ei = 0; ei < 8; ei++)
                out[(size_t)tt*EE + eg + 16*ei] = acc[ti][ei];
        }
    }
}

// ---------------------------------------------------------------------------
extern "C" void kernel_launch(void* const* d_in, const int* in_sizes, int n_in,
                              void* d_out, int out_size) {
    const float* q = (const float*)d_in[0];
    WArgs wa;
    for (int i = 0; i < 9; i++) wa.w[i] = (const float*)d_in[1 + i];
    const float* Wout = (const float*)d_in[10];
    float* out = (float*)d_out;

    // dynamic smem opt-in (host-side config; not a stream op -> capture-safe)
    cudaFuncSetAttribute(attn_kernel, cudaFuncAttributeMaxDynamicSharedMemorySize, 98304);
    cudaFuncSetAttribute(out_kernel,  cudaFuncAttributeMaxDynamicSharedMemorySize, 98304);

    proj_kernel<<<dim3(126, HH, 9), 64>>>(q, wa);
    attn_kernel<<<dim3(HH*BB, 8), 256, GG*KR*2*sizeof(float)>>>();
    out_kernel<<<(NTOK + 31)/32, 128, (32*129 + 128*128)*sizeof(float)>>>(Wout, out);
}

// round 2
// speedup vs baseline: 1.4768x; 1.4768x over previous
#include <cuda_runtime.h>

// ---------------------------------------------------------------------------
// Problem constants
// ---------------------------------------------------------------------------
#define HH   8
#define DD   128
#define KDD  16
#define EE   128
#define BB   16
#define GG   501
#define NPP  250
#define NTOK (BB*GG)      // 8016
#define NHALF (BB*NPP)    // 4000
#define KR   20           // padded smem row (16 data + 4 pad floats)
#define SCALE2 0.3606737602222409f   // (1/sqrt(16)) * log2(e)

// ---------------------------------------------------------------------------
// Scratch
// ---------------------------------------------------------------------------
__device__ float g_Q[HH*NTOK*KDD];
__device__ float g_K[HH*NTOK*KDD];
__device__ float g_V[HH*NTOK*KDD];
// [0]=W1(pick single) [1]=W2(pick vs K_pick) [2]=W3(pick vs K_del)
// [3]=W4(del single)  [4]=W5(del vs K_del)   [5]=W6(del vs K_pick)
__device__ float g_EQ[6][HH*NHALF*KDD];
__device__ float g_heads[HH*NTOK*KDD];

struct WArgs { const float* w[9]; };

// ---------------------------------------------------------------------------
// Kernel 1: projections as one folded GEMM per job.
// out[h,row,k] = sum_d q[row,d] * W[h,d,k]; fold (h,k)->col => [rows,128]x[128,128].
// 256 threads, 64-row x 128-col tile, 4x8 register blocking.
// Flat grid: jobs 0..2 have 126 tiles, jobs 3..8 have 63 tiles (756 blocks).
// ---------------------------------------------------------------------------
__global__ void __launch_bounds__(256, 2) proj_kernel(const float* __restrict__ q, WArgs a) {
    extern __shared__ float sm[];
    float* qs = sm;              // 64 * 132 (padded)
    float* ws = sm + 64*132;     // 128 * 128 (ws[d*128 + col], col = h*16+k)

    int bx = blockIdx.x;
    int job, tile;
    if (bx < 378) { job = bx / 126; tile = bx % 126; }
    else          { bx -= 378; job = 3 + bx / 63; tile = bx % 63; }

    const bool full = (job < 3);
    const int nrows = full ? NTOK : NHALF;
    const int r0 = tile * 64;
    const int tid = threadIdx.x;

    // ---- load weight tile: W[h][d][k] -> ws[d*128 + h*16 + k] ----
    const float* W = a.w[job];
    for (int i = tid; i < DD*DD; i += 256) {
        int d = i >> 7, col = i & 127;
        ws[i] = W[(col >> 4)*(DD*KDD) + d*KDD + (col & 15)];
    }

    // ---- load q tile (float4 coalesced) ----
    const int off = full ? 0 : ((job < 6) ? 1 : (NPP + 1));
    float4* qs4 = (float4*)qs;
    for (int i = tid; i < 64*32; i += 256) {
        int lr = i >> 5, d4 = i & 31;
        int rt = r0 + lr;
        float4 v = make_float4(0.f, 0.f, 0.f, 0.f);
        if (rt < nrows) {
            size_t srow;
            if (full) srow = (size_t)rt;
            else {
                int b = rt / NPP, p = rt % NPP;
                srow = (size_t)(b*GG + off + p);
            }
            v = ((const float4*)q)[srow*32 + d4];
        }
        qs4[lr*33 + d4] = v;   // row stride 132 floats = 33 float4
    }
    __syncthreads();

    // ---- compute: thread (rg,cg) -> rows rg*4..+3, cols cg*8..+7 ----
    const int cg = tid & 15;
    const int rg = tid >> 4;
    const float* qrow = qs + rg*4*132;
    const int c0 = cg*8;

    float acc[4][8];
#pragma unroll
    for (int i = 0; i < 4; i++)
#pragma unroll
        for (int j = 0; j < 8; j++) acc[i][j] = 0.f;

#pragma unroll 4
    for (int d = 0; d < DD; d++) {
        float4 w0 = *(const float4*)(ws + d*128 + c0);
        float4 w1 = *(const float4*)(ws + d*128 + c0 + 4);
        float qv[4];
#pragma unroll
        for (int ri = 0; ri < 4; ri++) qv[ri] = qrow[ri*132 + d];
#pragma unroll
        for (int ri = 0; ri < 4; ri++) {
            acc[ri][0] += qv[ri]*w0.x; acc[ri][1] += qv[ri]*w0.y;
            acc[ri][2] += qv[ri]*w0.z; acc[ri][3] += qv[ri]*w0.w;
            acc[ri][4] += qv[ri]*w1.x; acc[ri][5] += qv[ri]*w1.y;
            acc[ri][6] += qv[ri]*w1.z; acc[ri][7] += qv[ri]*w1.w;
        }
    }

    // ---- store: cols never cross h boundary (8 | 16) -> two float4 per row ----
    float* outp;
    if      (job == 0) outp = g_Q;
    else if (job == 1) outp = g_K;
    else if (job == 2) outp = g_V;
    else               outp = g_EQ[job-3];

    const int h  = c0 >> 4;
    const int k0 = c0 & 15;
#pragma unroll
    for (int ri = 0; ri < 4; ri++) {
        int rt = r0 + rg*4 + ri;
        if (rt < nrows) {
            float* o = outp + ((size_t)h*nrows + rt)*KDD + k0;
            *(float4*)(o)     = make_float4(acc[ri][0], acc[ri][1], acc[ri][2], acc[ri][3]);
            *(float4*)(o + 4) = make_float4(acc[ri][4], acc[ri][5], acc[ri][6], acc[ri][7]);
        }
    }
}

// ---------------------------------------------------------------------------
// Attention helpers
// ---------------------------------------------------------------------------
__device__ __forceinline__ float dot16v(const float* q,
        const float4 k0, const float4 k1, const float4 k2, const float4 k3) {
    float a = q[0]*k0.x + q[1]*k0.y + q[2]*k0.z + q[3]*k0.w;
    float b = q[4]*k1.x + q[5]*k1.y + q[6]*k1.z + q[7]*k1.w;
    float c = q[8]*k2.x + q[9]*k2.y + q[10]*k2.z + q[11]*k2.w;
    float d = q[12]*k3.x + q[13]*k3.y + q[14]*k3.z + q[15]*k3.w;
    return (a + b) + (c + d);
}

__device__ __forceinline__ void softupd(float s2,
        const float4 v0, const float4 v1, const float4 v2, const float4 v3,
        float& m, float& l, float* acc) {
    if (s2 > m) {
        float c = exp2f(m - s2);
        l *= c;
#pragma unroll
        for (int k = 0; k < 16; k++) acc[k] *= c;
        m = s2;
    }
    float w = exp2f(s2 - m);
    l += w;
    acc[0]  += w*v0.x; acc[1]  += w*v0.y; acc[2]  += w*v0.z; acc[3]  += w*v0.w;
    acc[4]  += w*v1.x; acc[5]  += w*v1.y; acc[6]  += w*v1.z; acc[7]  += w*v1.w;
    acc[8]  += w*v2.x; acc[9]  += w*v2.y; acc[10] += w*v2.z; acc[11] += w*v2.w;
    acc[12] += w*v3.x; acc[13] += w*v3.y; acc[14] += w*v3.z; acc[15] += w*v3.w;
}

// ---------------------------------------------------------------------------
// Kernel 2: fused attention per (h,b). grid (128, 8 q-tiles), block 256.
// ---------------------------------------------------------------------------
__global__ void __launch_bounds__(256, 1) attn_kernel() {
    extern __shared__ float sm[];
    float* Ks = sm;
    float* Vs = sm + GG*KR;

    const int hb   = blockIdx.x;
    const int tid  = threadIdx.x;
    const int lane = tid & 31;
    const int warp = tid >> 5;

    {
        const float4* K4 = (const float4*)(g_K + (size_t)hb * GG * KDD);
        const float4* V4 = (const float4*)(g_V + (size_t)hb * GG * KDD);
        float4* Ks4 = (float4*)Ks;
        float4* Vs4 = (float4*)Vs;
        for (int i = tid; i < GG*4; i += 256) {
            int j = i >> 2, k4 = i & 3;
            Ks4[j*5 + k4] = K4[i];
            Vs4[j*5 + k4] = V4[i];
        }
    }
    __syncthreads();

    const int qbase = blockIdx.y * 64;

    for (int gi = warp; gi < 16; gi += 8) {
        const int n0 = qbase + gi*4;
        if (n0 >= GG) continue;

        float m[4], l[4], acc[4][16], qv[4][16];
        bool valid[4];
#pragma unroll
        for (int i = 0; i < 4; i++) {
            int n = n0 + i;
            valid[i] = (n < GG);
            m[i] = -1e30f; l[i] = 0.f;
            const float* qp = g_Q + ((size_t)hb*GG + (valid[i] ? n : 0))*KDD;
#pragma unroll
            for (int k = 0; k < 16; k++) {
                acc[i][k] = 0.f;
                qv[i][k] = valid[i] ? qp[k] : 0.f;
            }
        }

        // ---- base: all G keys ----
        for (int j = lane; j < GG; j += 32) {
            const float4* kr = (const float4*)(Ks + j*KR);
            const float4* vr = (const float4*)(Vs + j*KR);
            float4 k0 = kr[0], k1 = kr[1], k2 = kr[2], k3 = kr[3];
            float4 v0 = vr[0], v1 = vr[1], v2 = vr[2], v3 = vr[3];
#pragma unroll
            for (int i = 0; i < 4; i++) {
                float s2 = dot16v(qv[i], k0,k1,k2,k3) * SCALE2;
                softupd(s2, v0,v1,v2,v3, m[i], l[i], acc[i]);
            }
        }

        bool pk[4], dl[4];
#pragma unroll
        for (int i = 0; i < 4; i++) {
            int n = n0 + i;
            pk[i] = (n >= 1) && (n <= NPP);
            dl[i] = (n >= NPP+1) && (n < GG);
        }

        // ---- extras A: pick keys 1..NPP ----
#pragma unroll
        for (int i = 0; i < 4; i++) {
            int n = n0 + i;
            if (pk[i] || dl[i]) {
                int p = pk[i] ? (n-1) : (n-NPP-1);
                const float* src = (pk[i] ? g_EQ[1] : g_EQ[5]) + ((size_t)hb*NPP + p)*KDD;
#pragma unroll
                for (int k = 0; k < 16; k++) qv[i][k] = src[k];
            }
        }
        for (int j = lane; j < NPP; j += 32) {
            const int key = 1 + j;
            const float4* kr = (const float4*)(Ks + key*KR);
            const float4* vr = (const float4*)(Vs + key*KR);
            float4 k0 = kr[0], k1 = kr[1], k2 = kr[2], k3 = kr[3];
            float4 v0 = vr[0], v1 = vr[1], v2 = vr[2], v3 = vr[3];
#pragma unroll
            for (int i = 0; i < 4; i++) {
                float s2 = dot16v(qv[i], k0,k1,k2,k3) * SCALE2;
                if (!(pk[i] || dl[i])) s2 = -1e30f;
                softupd(s2, v0,v1,v2,v3, m[i], l[i], acc[i]);
            }
        }

        // ---- extras B: delivery keys NPP+1..2NPP ----
#pragma unroll
        for (int i = 0; i < 4; i++) {
            int n = n0 + i;
            if (pk[i] || dl[i]) {
                int p = pk[i] ? (n-1) : (n-NPP-1);
                const float* src = (pk[i] ? g_EQ[2] : g_EQ[4]) + ((size_t)hb*NPP + p)*KDD;
#pragma unroll
                for (int k = 0; k < 16; k++) qv[i][k] = src[k];
            }
        }
        for (int j = lane; j < NPP; j += 32) {
            const int key = NPP + 1 + j;
            const float4* kr = (const float4*)(Ks + key*KR);
            const float4* vr = (const float4*)(Vs + key*KR);
            float4 k0 = kr[0], k1 = kr[1], k2 = kr[2], k3 = kr[3];
            float4 v0 = vr[0], v1 = vr[1], v2 = vr[2], v3 = vr[3];
#pragma unroll
            for (int i = 0; i < 4; i++) {
                float s2 = dot16v(qv[i], k0,k1,k2,k3) * SCALE2;
                if (!(pk[i] || dl[i])) s2 = -1e30f;
                softupd(s2, v0,v1,v2,v3, m[i], l[i], acc[i]);
            }
        }

        // ---- single paired extras ----
#pragma unroll
        for (int i = 0; i < 4; i++) {
            if (lane == i) {
                int n = n0 + i;
                if (pk[i] || dl[i]) {
                    int p   = pk[i] ? (n-1) : (n-NPP-1);
                    int key = pk[i] ? (NPP+1+p) : (1+p);
                    const float* sq = (pk[i] ? g_EQ[0] : g_EQ[3]) + ((size_t)hb*NPP + p)*KDD;
                    float qq[16];
#pragma unroll
                    for (int k = 0; k < 16; k++) qq[k] = sq[k];
                    const float4* kr = (const float4*)(Ks + key*KR);
                    const float4* vr = (const float4*)(Vs + key*KR);
                    float s2 = dot16v(qq, kr[0],kr[1],kr[2],kr[3]) * SCALE2;
                    softupd(s2, vr[0],vr[1],vr[2],vr[3], m[i], l[i], acc[i]);
                }
            }
        }

        // ---- warp reduction + store ----
#pragma unroll
        for (int i = 0; i < 4; i++) {
            float M = m[i];
#pragma unroll
            for (int o = 16; o > 0; o >>= 1)
                M = fmaxf(M, __shfl_xor_sync(0xffffffffu, M, o));
            float c = exp2f(m[i] - M);
            float li = l[i] * c;
#pragma unroll
            for (int o = 16; o > 0; o >>= 1)
                li += __shfl_xor_sync(0xffffffffu, li, o);
#pragma unroll
            for (int k = 0; k < 16; k++) {
                float a = acc[i][k] * c;
#pragma unroll
                for (int o = 16; o > 0; o >>= 1)
                    a += __shfl_xor_sync(0xffffffffu, a, o);
                acc[i][k] = a;
            }
            if (lane == 0 && valid[i]) {
                float inv = 1.0f / li;
                float* o = g_heads + ((size_t)hb*GG + n0 + i)*KDD;
#pragma unroll
                for (int k = 0; k < 16; k++) o[k] = acc[i][k] * inv;
            }
        }
    }
}

// ---------------------------------------------------------------------------
// Kernel 3: output projection.
// ---------------------------------------------------------------------------
__global__ void out_kernel(const float* __restrict__ Wout, float* __restrict__ out) {
    extern __shared__ float sm[];
    float* hs = sm;
    float* ws = sm + 32*129;

    const int tid = threadIdx.x;
    const int t0  = blockIdx.x * 32;

    for (int i = tid; i < HH*KDD*EE; i += 128) ws[i] = Wout[i];
    for (int i = tid; i < 32*HH*KDD; i += 128) {
        int t = i >> 7, hk = i & 127;
        int tt = t0 + t;
        float v = 0.f;
        if (tt < NTOK)
            v = g_heads[((size_t)(hk >> 4)*NTOK + tt)*KDD + (hk & 15)];
        hs[t*129 + hk] = v;
    }
    __syncthreads();

    const int eg = tid & 15;
    const int tg = tid >> 4;
    float acc[4][8];
#pragma unroll
    for (int ti = 0; ti < 4; ti++)
#pragma unroll
        for (int ei = 0; ei < 8; ei++) acc[ti][ei] = 0.f;

#pragma unroll 4
    for (int hk = 0; hk < 128; hk++) {
        float w[8], hv[4];
#pragma unroll
        for (int ei = 0; ei < 8; ei++) w[ei] = ws[hk*128 + eg + 16*ei];
#pragma unroll
        for (int ti = 0; ti < 4; ti++) hv[ti] = hs[(tg*4 + ti)*129 + hk];
#pragma unroll
        for (int ti = 0; ti < 4; ti++)
#pragma unroll
            for (int ei = 0; ei < 8; ei++) acc[ti][ei] += hv[ti]*w[ei];
    }

#pragma unroll
    for (int ti = 0; ti < 4; ti++) {
        int tt = t0 + tg*4 + ti;
        if (tt < NTOK) {
#pragma unroll
            for (int ei = 0; ei < 8; ei++)
                out[(size_t)tt*EE + eg + 16*ei] = acc[ti][ei];
        }
    }
}

// ---------------------------------------------------------------------------
extern "C" void kernel_launch(void* const* d_in, const int* in_sizes, int n_in,
                              void* d_out, int out_size) {
    const float* q = (const float*)d_in[0];
    WArgs wa;
    for (int i = 0; i < 9; i++) wa.w[i] = (const float*)d_in[1 + i];
    const float* Wout = (const float*)d_in[10];
    float* out = (float*)d_out;

    const int projSmem = (64*132 + 128*128) * sizeof(float);   // 99328 B
    cudaFuncSetAttribute(proj_kernel, cudaFuncAttributeMaxDynamicSharedMemorySize, projSmem);
    cudaFuncSetAttribute(attn_kernel, cudaFuncAttributeMaxDynamicSharedMemorySize, 98304);
    cudaFuncSetAttribute(out_kernel,  cudaFuncAttributeMaxDynamicSharedMemorySize, 98304);

    proj_kernel<<<756, 256, projSmem>>>(q, wa);
    attn_kernel<<<dim3(HH*BB, 8), 256, GG*KR*2*sizeof(float)>>>();
    out_kernel<<<(NTOK + 31)/32, 128, (32*129 + 128*128)*sizeof(float)>>>(Wout, out);
}

// round 3
// speedup vs baseline: 1.6900x; 1.1443x over previous
#include <cuda_runtime.h>

// ---------------------------------------------------------------------------
// Problem constants
// ---------------------------------------------------------------------------
#define HH   8
#define DD   128
#define KDD  16
#define EE   128
#define BB   16
#define GG   501
#define NPP  250
#define NTOK (BB*GG)      // 8016
#define NHALF (BB*NPP)    // 4000
#define SCALE2 0.3606737602222409f   // (1/sqrt(16)) * log2(e)

// ---------------------------------------------------------------------------
// Scratch
// ---------------------------------------------------------------------------
__device__ float g_Q[HH*NTOK*KDD];
__device__ float g_K[HH*NTOK*KDD];
__device__ float g_V[HH*NTOK*KDD];
// [0]=W1(pick single) [1]=W2(pick vs K_pick) [2]=W3(pick vs K_del)
// [3]=W4(del single)  [4]=W5(del vs K_del)   [5]=W6(del vs K_pick)
__device__ float g_EQ[6][HH*NHALF*KDD];
__device__ float g_heads[HH*NTOK*KDD];

struct WArgs { const float* w[9]; };

// ---------------------------------------------------------------------------
// Kernel 1: projections as folded GEMMs.
// out[h,row,k] = sum_d q[row,d]*W[h,d,k]; (h,k)->col: [rows,128]x[128,128].
// Tile: 64 rows x 64 cols per block (col half = blockIdx.y), 256 threads,
// 4x4 register blocking. smem 66.5KB -> 3 blocks/SM.
// ---------------------------------------------------------------------------
__global__ void __launch_bounds__(256, 3) proj_kernel(const float* __restrict__ q, WArgs a) {
    extern __shared__ float sm[];
    float* qs = sm;              // 64 * 132 (padded; row stride 33 float4)
    float* ws = sm + 64*132;     // 128 * 64  (ws[d*64 + col])

    int bx = blockIdx.x;
    const int ch = blockIdx.y;   // column half (0/1)
    int job, tile;
    if (bx < 378) { job = bx / 126; tile = bx % 126; }
    else          { bx -= 378; job = 3 + bx / 63; tile = bx % 63; }

    const bool full = (job < 3);
    const int nrows = full ? NTOK : NHALF;
    const int r0 = tile * 64;
    const int tid = threadIdx.x;

    // ---- weight tile: cols [ch*64, ch*64+64) ----
    const float* W = a.w[job];
    for (int i = tid; i < DD*64; i += 256) {
        int d = i >> 6, col = i & 63;
        int gcol = ch*64 + col;
        ws[i] = W[(gcol >> 4)*(DD*KDD) + d*KDD + (gcol & 15)];
    }

    // ---- q tile (float4 coalesced) ----
    const int off = full ? 0 : ((job < 6) ? 1 : (NPP + 1));
    float4* qs4 = (float4*)qs;
    for (int i = tid; i < 64*32; i += 256) {
        int lr = i >> 5, d4 = i & 31;
        int rt = r0 + lr;
        float4 v = make_float4(0.f, 0.f, 0.f, 0.f);
        if (rt < nrows) {
            size_t srow;
            if (full) srow = (size_t)rt;
            else {
                int b = rt / NPP, p = rt % NPP;
                srow = (size_t)(b*GG + off + p);
            }
            v = ((const float4*)q)[srow*32 + d4];
        }
        qs4[lr*33 + d4] = v;
    }
    __syncthreads();

    // ---- compute: thread (rg,cg) -> rows rg*4..+3, local cols cg*4..+3 ----
    const int cg = tid & 15;
    const int rg = tid >> 4;
    const float* qrow = qs + rg*4*132;
    const int c0 = cg*4;

    float acc[4][4];
#pragma unroll
    for (int i = 0; i < 4; i++)
#pragma unroll
        for (int j = 0; j < 4; j++) acc[i][j] = 0.f;

#pragma unroll 8
    for (int d = 0; d < DD; d++) {
        float4 w = *(const float4*)(ws + d*64 + c0);
        float qv[4];
#pragma unroll
        for (int ri = 0; ri < 4; ri++) qv[ri] = qrow[ri*132 + d];
#pragma unroll
        for (int ri = 0; ri < 4; ri++) {
            acc[ri][0] += qv[ri]*w.x; acc[ri][1] += qv[ri]*w.y;
            acc[ri][2] += qv[ri]*w.z; acc[ri][3] += qv[ri]*w.w;
        }
    }

    float* outp;
    if      (job == 0) outp = g_Q;
    else if (job == 1) outp = g_K;
    else if (job == 2) outp = g_V;
    else               outp = g_EQ[job-3];

    const int gcol0 = ch*64 + c0;       // multiple of 4, within one h (4|16)
    const int h  = gcol0 >> 4;
    const int k0 = gcol0 & 15;
#pragma unroll
    for (int ri = 0; ri < 4; ri++) {
        int rt = r0 + rg*4 + ri;
        if (rt < nrows) {
            float* o = outp + ((size_t)h*nrows + rt)*KDD + k0;
            *(float4*)o = make_float4(acc[ri][0], acc[ri][1], acc[ri][2], acc[ri][3]);
        }
    }
}

// ---------------------------------------------------------------------------
// Attention helpers
// ---------------------------------------------------------------------------
__device__ __forceinline__ float dot16v(const float* q,
        const float4 k0, const float4 k1, const float4 k2, const float4 k3) {
    float a = q[0]*k0.x + q[1]*k0.y + q[2]*k0.z + q[3]*k0.w;
    float b = q[4]*k1.x + q[5]*k1.y + q[6]*k1.z + q[7]*k1.w;
    float c = q[8]*k2.x + q[9]*k2.y + q[10]*k2.z + q[11]*k2.w;
    float d = q[12]*k3.x + q[13]*k3.y + q[14]*k3.z + q[15]*k3.w;
    return (a + b) + (c + d);
}

__device__ __forceinline__ void softupd(float s2,
        const float4 v0, const float4 v1, const float4 v2, const float4 v3,
        float& m, float& l, float* acc) {
    if (s2 > m) {                       // rare rescale
        float c = exp2f(m - s2);
        l *= c;
#pragma unroll
        for (int k = 0; k < 16; k++) acc[k] *= c;
        m = s2;
    }
    float w = exp2f(s2 - m);            // masked (s2=-1e30) -> 0
    l += w;
    acc[0]  += w*v0.x; acc[1]  += w*v0.y; acc[2]  += w*v0.z; acc[3]  += w*v0.w;
    acc[4]  += w*v1.x; acc[5]  += w*v1.y; acc[6]  += w*v1.z; acc[7]  += w*v1.w;
    acc[8]  += w*v2.x; acc[9]  += w*v2.y; acc[10] += w*v2.z; acc[11] += w*v2.w;
    acc[12] += w*v3.x; acc[13] += w*v3.y; acc[14] += w*v3.z; acc[15] += w*v3.w;
}

// ---------------------------------------------------------------------------
// Kernel 2: attention, one query per thread (no reductions).
// grid (HB=128, 4 q-chunks of 128), block 128.
// K/V rows in unpadded smem; all lanes read the same row -> broadcast LDS.
// ---------------------------------------------------------------------------
__global__ void __launch_bounds__(128, 3) attn_kernel() {
    extern __shared__ float sm[];
    float4* Ks4 = (float4*)sm;              // GG*4 float4
    float4* Vs4 = ((float4*)sm) + GG*4;

    const int hb  = blockIdx.x;
    const int tid = threadIdx.x;

    {   // straight contiguous copy (layout identical, no padding needed)
        const float4* K4 = (const float4*)(g_K + (size_t)hb * GG * KDD);
        const float4* V4 = (const float4*)(g_V + (size_t)hb * GG * KDD);
        for (int i = tid; i < GG*4; i += 128) {
            Ks4[i] = K4[i];
            Vs4[i] = V4[i];
        }
    }
    __syncthreads();

    const int n = blockIdx.y * 128 + tid;
    const bool valid = (n < GG);
    const int nn = valid ? n : 0;

    float qv[16], acc[16];
    float m = -1e30f, l = 0.f;
    {
        const float4* qp = (const float4*)(g_Q + ((size_t)hb*GG + nn)*KDD);
#pragma unroll
        for (int t = 0; t < 4; t++) {
            float4 v = qp[t];
            qv[t*4+0] = v.x; qv[t*4+1] = v.y; qv[t*4+2] = v.z; qv[t*4+3] = v.w;
        }
#pragma unroll
        for (int k = 0; k < 16; k++) acc[k] = 0.f;
    }

    // ---- base: all G keys ----
    for (int j = 0; j < GG; j++) {
        float4 k0 = Ks4[j*4+0], k1 = Ks4[j*4+1], k2 = Ks4[j*4+2], k3 = Ks4[j*4+3];
        float4 v0 = Vs4[j*4+0], v1 = Vs4[j*4+1], v2 = Vs4[j*4+2], v3 = Vs4[j*4+3];
        float s2 = dot16v(qv, k0,k1,k2,k3) * SCALE2;
        softupd(s2, v0,v1,v2,v3, m, l, acc);
    }

    const bool pk = (n >= 1) && (n <= NPP);
    const bool dl = (n >= NPP+1) && (n < GG);
    const bool ex = pk || dl;
    const int  p  = pk ? (n-1) : (n-NPP-1);

    // ---- extras A: pick keys 1..NPP; pick q -> EQ1 (W2), del q -> EQ5 (W6) ----
    if (ex) {
        const float4* ep = (const float4*)((pk ? g_EQ[1] : g_EQ[5]) + ((size_t)hb*NPP + p)*KDD);
#pragma unroll
        for (int t = 0; t < 4; t++) {
            float4 v = ep[t];
            qv[t*4+0] = v.x; qv[t*4+1] = v.y; qv[t*4+2] = v.z; qv[t*4+3] = v.w;
        }
    }
    for (int j = 1; j <= NPP; j++) {
        float4 k0 = Ks4[j*4+0], k1 = Ks4[j*4+1], k2 = Ks4[j*4+2], k3 = Ks4[j*4+3];
        float4 v0 = Vs4[j*4+0], v1 = Vs4[j*4+1], v2 = Vs4[j*4+2], v3 = Vs4[j*4+3];
        float s2 = ex ? (dot16v(qv, k0,k1,k2,k3) * SCALE2) : -1e30f;
        softupd(s2, v0,v1,v2,v3, m, l, acc);
    }

    // ---- extras B: del keys NPP+1..2NPP; pick q -> EQ2 (W3), del q -> EQ4 (W5) ----
    if (ex) {
        const float4* ep = (const float4*)((pk ? g_EQ[2] : g_EQ[4]) + ((size_t)hb*NPP + p)*KDD);
#pragma unroll
        for (int t = 0; t < 4; t++) {
            float4 v = ep[t];
            qv[t*4+0] = v.x; qv[t*4+1] = v.y; qv[t*4+2] = v.z; qv[t*4+3] = v.w;
        }
    }
    for (int j = NPP+1; j <= 2*NPP; j++) {
        float4 k0 = Ks4[j*4+0], k1 = Ks4[j*4+1], k2 = Ks4[j*4+2], k3 = Ks4[j*4+3];
        float4 v0 = Vs4[j*4+0], v1 = Vs4[j*4+1], v2 = Vs4[j*4+2], v3 = Vs4[j*4+3];
        float s2 = ex ? (dot16v(qv, k0,k1,k2,k3) * SCALE2) : -1e30f;
        softupd(s2, v0,v1,v2,v3, m, l, acc);
    }

    // ---- single paired extra: pick q -> K_del[p] (EQ0/W1), del q -> K_pick[p] (EQ3/W4) ----
    if (ex) {
        const int key = pk ? (NPP+1+p) : (1+p);
        const float4* ep = (const float4*)((pk ? g_EQ[0] : g_EQ[3]) + ((size_t)hb*NPP + p)*KDD);
#pragma unroll
        for (int t = 0; t < 4; t++) {
            float4 v = ep[t];
            qv[t*4+0] = v.x; qv[t*4+1] = v.y; qv[t*4+2] = v.z; qv[t*4+3] = v.w;
        }
        float s2 = dot16v(qv, Ks4[key*4+0], Ks4[key*4+1], Ks4[key*4+2], Ks4[key*4+3]) * SCALE2;
        softupd(s2, Vs4[key*4+0], Vs4[key*4+1], Vs4[key*4+2], Vs4[key*4+3], m, l, acc);
    }

    // ---- finalize ----
    if (valid) {
        float inv = 1.0f / l;
        float4* o = (float4*)(g_heads + ((size_t)hb*GG + n)*KDD);
#pragma unroll
        for (int t = 0; t < 4; t++)
            o[t] = make_float4(acc[t*4+0]*inv, acc[t*4+1]*inv, acc[t*4+2]*inv, acc[t*4+3]*inv);
    }
}

// ---------------------------------------------------------------------------
// Kernel 3: output projection. out[t,e] = sum_hk heads[t,hk]*Wout[hk,e]
// ---------------------------------------------------------------------------
__global__ void out_kernel(const float* __restrict__ Wout, float* __restrict__ out) {
    extern __shared__ float sm[];
    float* hs = sm;                  // 32 * 129
    float* ws = sm + 32*129;         // 128 * 128

    const int tid = threadIdx.x;
    const int t0  = blockIdx.x * 32;

    for (int i = tid; i < HH*KDD*EE; i += 128) ws[i] = Wout[i];
    for (int i = tid; i < 32*HH*KDD; i += 128) {
        int t = i >> 7, hk = i & 127;
        int tt = t0 + t;
        float v = 0.f;
        if (tt < NTOK)
            v = g_heads[((size_t)(hk >> 4)*NTOK + tt)*KDD + (hk & 15)];
        hs[t*129 + hk] = v;
    }
    __syncthreads();

    const int eg = tid & 15;
    const int tg = tid >> 4;
    float acc[4][8];
#pragma unroll
    for (int ti = 0; ti < 4; ti++)
#pragma unroll
        for (int ei = 0; ei < 8; ei++) acc[ti][ei] = 0.f;

#pragma unroll 4
    for (int hk = 0; hk < 128; hk++) {
        float w[8], hv[4];
#pragma unroll
        for (int ei = 0; ei < 8; ei++) w[ei] = ws[hk*128 + eg + 16*ei];
#pragma unroll
        for (int ti = 0; ti < 4; ti++) hv[ti] = hs[(tg*4 + ti)*129 + hk];
#pragma unroll
        for (int ti = 0; ti < 4; ti++)
#pragma unroll
            for (int ei = 0; ei < 8; ei++) acc[ti][ei] += hv[ti]*w[ei];
    }

#pragma unroll
    for (int ti = 0; ti < 4; ti++) {
        int tt = t0 + tg*4 + ti;
        if (tt < NTOK) {
#pragma unroll
            for (int ei = 0; ei < 8; ei++)
                out[(size_t)tt*EE + eg + 16*ei] = acc[ti][ei];
        }
    }
}

// ---------------------------------------------------------------------------
extern "C" void kernel_launch(void* const* d_in, const int* in_sizes, int n_in,
                              void* d_out, int out_size) {
    const float* q = (const float*)d_in[0];
    WArgs wa;
    for (int i = 0; i < 9; i++) wa.w[i] = (const float*)d_in[1 + i];
    const float* Wout = (const float*)d_in[10];
    float* out = (float*)d_out;

    const int projSmem = (64*132 + 128*64) * sizeof(float);    // 66560 B
    const int attnSmem = GG*KDD*2*sizeof(float);               // 64128 B
    const int outSmem  = (32*129 + 128*128) * sizeof(float);
    cudaFuncSetAttribute(proj_kernel, cudaFuncAttributeMaxDynamicSharedMemorySize, projSmem);
    cudaFuncSetAttribute(attn_kernel, cudaFuncAttributeMaxDynamicSharedMemorySize, attnSmem);
    cudaFuncSetAttribute(out_kernel,  cudaFuncAttributeMaxDynamicSharedMemorySize, outSmem);

    proj_kernel<<<dim3(756, 2), 256, projSmem>>>(q, wa);
    attn_kernel<<<dim3(HH*BB, 4), 128, attnSmem>>>();
    out_kernel<<<(NTOK + 31)/32, 128, outSmem>>>(Wout, out);
}

// round 4
// speedup vs baseline: 2.0066x; 1.1873x over previous
#include <cuda_runtime.h>

// ---------------------------------------------------------------------------
// Problem constants
// ---------------------------------------------------------------------------
#define HH   8
#define DD   128
#define KDD  16
#define EE   128
#define BB   16
#define GG   501
#define NPP  250
#define NTOK (BB*GG)      // 8016
#define NHALF (BB*NPP)    // 4000
#define SCALE2 0.3606737602222409f   // (1/sqrt(16)) * log2(e)

// ---------------------------------------------------------------------------
// Scratch
// ---------------------------------------------------------------------------
__device__ float g_Q[HH*NTOK*KDD];
__device__ float g_K[HH*NTOK*KDD];
__device__ float g_V[HH*NTOK*KDD];
// [0]=W1(pick single) [1]=W2(pick vs K_pick) [2]=W3(pick vs K_del)
// [3]=W4(del single)  [4]=W5(del vs K_del)   [5]=W6(del vs K_pick)
__device__ float g_EQ[6][HH*NHALF*KDD];
__device__ float g_heads[HH*NTOK*KDD];

struct WArgs { const float* w[9]; };

__device__ __forceinline__ float ex2(float x) {
    float r;
    asm("ex2.approx.f32 %0, %1;" : "=f"(r) : "f"(x));
    return r;
}

// ---------------------------------------------------------------------------
// Kernel 1: projections as folded GEMMs.
// out[h,row,k] = sum_d q[row,d]*W[h,d,k]; (h,k)->col: [rows,128]x[128,128].
// 64 rows x 64 cols per block, 256 threads, 4x4 register blocking.
// ---------------------------------------------------------------------------
__global__ void __launch_bounds__(256, 3) proj_kernel(const float* __restrict__ q, WArgs a) {
    extern __shared__ float sm[];
    float* qs = sm;              // 64 * 132 (padded)
    float* ws = sm + 64*132;     // 128 * 64

    int bx = blockIdx.x;
    const int ch = blockIdx.y;   // column half (0/1)
    int job, tile;
    if (bx < 378) { job = bx / 126; tile = bx % 126; }
    else          { bx -= 378; job = 3 + bx / 63; tile = bx % 63; }

    const bool full = (job < 3);
    const int nrows = full ? NTOK : NHALF;
    const int r0 = tile * 64;
    const int tid = threadIdx.x;

    // ---- weight tile (float4): ws4[d*16 + c4] = W4[h*512 + d*4 + k4] ----
    {
        const float4* W4 = (const float4*)a.w[job];
        float4* ws4 = (float4*)ws;
        for (int i = tid; i < DD*16; i += 256) {
            int d = i >> 4, c4 = i & 15;
            int gc4 = ch*16 + c4;               // global float4-col
            ws4[i] = W4[(gc4 >> 2)*(DD*4) + d*4 + (gc4 & 3)];
        }
    }

    // ---- q tile (float4 coalesced) ----
    const int off = full ? 0 : ((job < 6) ? 1 : (NPP + 1));
    float4* qs4 = (float4*)qs;
    for (int i = tid; i < 64*32; i += 256) {
        int lr = i >> 5, d4 = i & 31;
        int rt = r0 + lr;
        float4 v = make_float4(0.f, 0.f, 0.f, 0.f);
        if (rt < nrows) {
            size_t srow;
            if (full) srow = (size_t)rt;
            else {
                int b = rt / NPP, p = rt % NPP;
                srow = (size_t)(b*GG + off + p);
            }
            v = ((const float4*)q)[srow*32 + d4];
        }
        qs4[lr*33 + d4] = v;
    }
    __syncthreads();

    const int cg = tid & 15;
    const int rg = tid >> 4;
    const float* qrow = qs + rg*4*132;
    const int c0 = cg*4;

    float acc[4][4];
#pragma unroll
    for (int i = 0; i < 4; i++)
#pragma unroll
        for (int j = 0; j < 4; j++) acc[i][j] = 0.f;

#pragma unroll 8
    for (int d = 0; d < DD; d++) {
        float4 w = *(const float4*)(ws + d*64 + c0);
        float qv[4];
#pragma unroll
        for (int ri = 0; ri < 4; ri++) qv[ri] = qrow[ri*132 + d];
#pragma unroll
        for (int ri = 0; ri < 4; ri++) {
            acc[ri][0] += qv[ri]*w.x; acc[ri][1] += qv[ri]*w.y;
            acc[ri][2] += qv[ri]*w.z; acc[ri][3] += qv[ri]*w.w;
        }
    }

    float* outp;
    if      (job == 0) outp = g_Q;
    else if (job == 1) outp = g_K;
    else if (job == 2) outp = g_V;
    else               outp = g_EQ[job-3];

    const int gcol0 = ch*64 + c0;
    const int h  = gcol0 >> 4;
    const int k0 = gcol0 & 15;
#pragma unroll
    for (int ri = 0; ri < 4; ri++) {
        int rt = r0 + rg*4 + ri;
        if (rt < nrows) {
            float* o = outp + ((size_t)h*nrows + rt)*KDD + k0;
            *(float4*)o = make_float4(acc[ri][0], acc[ri][1], acc[ri][2], acc[ri][3]);
        }
    }
}

// ---------------------------------------------------------------------------
// Attention helpers (branchless, no online max: |s2| << 127 so exp2 is safe)
// ---------------------------------------------------------------------------
__device__ __forceinline__ float dot16v(const float* q,
        const float4 k0, const float4 k1, const float4 k2, const float4 k3) {
    float a = q[0]*k0.x + q[1]*k0.y + q[2]*k0.z + q[3]*k0.w;
    float b = q[4]*k1.x + q[5]*k1.y + q[6]*k1.z + q[7]*k1.w;
    float c = q[8]*k2.x + q[9]*k2.y + q[10]*k2.z + q[11]*k2.w;
    float d = q[12]*k3.x + q[13]*k3.y + q[14]*k3.z + q[15]*k3.w;
    return (a + b) + (c + d);
}

__device__ __forceinline__ void accum(float w,
        const float4 v0, const float4 v1, const float4 v2, const float4 v3,
        float& l, float* acc) {
    l += w;
    acc[0]  += w*v0.x; acc[1]  += w*v0.y; acc[2]  += w*v0.z; acc[3]  += w*v0.w;
    acc[4]  += w*v1.x; acc[5]  += w*v1.y; acc[6]  += w*v1.z; acc[7]  += w*v1.w;
    acc[8]  += w*v2.x; acc[9]  += w*v2.y; acc[10] += w*v2.z; acc[11] += w*v2.w;
    acc[12] += w*v3.x; acc[13] += w*v3.y; acc[14] += w*v3.z; acc[15] += w*v3.w;
}

// ---------------------------------------------------------------------------
// Kernel 2: attention, one query per thread, branchless exp accumulation.
// grid (HB=128, 4 q-chunks of 128), block 128.
// ---------------------------------------------------------------------------
__global__ void __launch_bounds__(128, 3) attn_kernel() {
    extern __shared__ float sm[];
    float4* Ks4 = (float4*)sm;              // GG*4 float4
    float4* Vs4 = ((float4*)sm) + GG*4;

    const int hb  = blockIdx.x;
    const int tid = threadIdx.x;

    {
        const float4* K4 = (const float4*)(g_K + (size_t)hb * GG * KDD);
        const float4* V4 = (const float4*)(g_V + (size_t)hb * GG * KDD);
        for (int i = tid; i < GG*4; i += 128) {
            Ks4[i] = K4[i];
            Vs4[i] = V4[i];
        }
    }
    __syncthreads();

    const int n = blockIdx.y * 128 + tid;
    const bool valid = (n < GG);
    const int nn = valid ? n : 0;

    float qv[16], acc[16];
    float l = 0.f;
    {
        const float4* qp = (const float4*)(g_Q + ((size_t)hb*GG + nn)*KDD);
#pragma unroll
        for (int t = 0; t < 4; t++) {
            float4 v = qp[t];
            qv[t*4+0] = v.x*SCALE2; qv[t*4+1] = v.y*SCALE2;
            qv[t*4+2] = v.z*SCALE2; qv[t*4+3] = v.w*SCALE2;
        }
#pragma unroll
        for (int k = 0; k < 16; k++) acc[k] = 0.f;
    }

    // ---- base: all G keys ----
#pragma unroll 2
    for (int j = 0; j < GG; j++) {
        float4 k0 = Ks4[j*4+0], k1 = Ks4[j*4+1], k2 = Ks4[j*4+2], k3 = Ks4[j*4+3];
        float w = ex2(dot16v(qv, k0,k1,k2,k3));
        accum(w, Vs4[j*4+0], Vs4[j*4+1], Vs4[j*4+2], Vs4[j*4+3], l, acc);
    }

    const bool pk = (n >= 1) && (n <= NPP);
    const bool dl = (n >= NPP+1) && (n < GG);
    const bool ex = pk || dl;
    const int  p  = pk ? (n-1) : (n-NPP-1);

    // ---- extras A: pick keys 1..NPP; pick q -> EQ1 (W2), del q -> EQ5 (W6) ----
    if (ex) {
        const float4* ep = (const float4*)((pk ? g_EQ[1] : g_EQ[5]) + ((size_t)hb*NPP + p)*KDD);
#pragma unroll
        for (int t = 0; t < 4; t++) {
            float4 v = ep[t];
            qv[t*4+0] = v.x*SCALE2; qv[t*4+1] = v.y*SCALE2;
            qv[t*4+2] = v.z*SCALE2; qv[t*4+3] = v.w*SCALE2;
        }
    }
#pragma unroll 2
    for (int j = 1; j <= NPP; j++) {
        float4 k0 = Ks4[j*4+0], k1 = Ks4[j*4+1], k2 = Ks4[j*4+2], k3 = Ks4[j*4+3];
        float w = ex ? ex2(dot16v(qv, k0,k1,k2,k3)) : 0.f;
        accum(w, Vs4[j*4+0], Vs4[j*4+1], Vs4[j*4+2], Vs4[j*4+3], l, acc);
    }

    // ---- extras B: del keys NPP+1..2NPP; pick q -> EQ2 (W3), del q -> EQ4 (W5) ----
    if (ex) {
        const float4* ep = (const float4*)((pk ? g_EQ[2] : g_EQ[4]) + ((size_t)hb*NPP + p)*KDD);
#pragma unroll
        for (int t = 0; t < 4; t++) {
            float4 v = ep[t];
            qv[t*4+0] = v.x*SCALE2; qv[t*4+1] = v.y*SCALE2;
            qv[t*4+2] = v.z*SCALE2; qv[t*4+3] = v.w*SCALE2;
        }
    }
#pragma unroll 2
    for (int j = NPP+1; j <= 2*NPP; j++) {
        float4 k0 = Ks4[j*4+0], k1 = Ks4[j*4+1], k2 = Ks4[j*4+2], k3 = Ks4[j*4+3];
        float w = ex ? ex2(dot16v(qv, k0,k1,k2,k3)) : 0.f;
        accum(w, Vs4[j*4+0], Vs4[j*4+1], Vs4[j*4+2], Vs4[j*4+3], l, acc);
    }

    // ---- single paired extra: pick q -> K_del[p] (EQ0/W1), del q -> K_pick[p] (EQ3/W4) ----
    if (ex) {
        const int key = pk ? (NPP+1+p) : (1+p);
        const float4* ep = (const float4*)((pk ? g_EQ[0] : g_EQ[3]) + ((size_t)hb*NPP + p)*KDD);
#pragma unroll
        for (int t = 0; t < 4; t++) {
            float4 v = ep[t];
            qv[t*4+0] = v.x*SCALE2; qv[t*4+1] = v.y*SCALE2;
            qv[t*4+2] = v.z*SCALE2; qv[t*4+3] = v.w*SCALE2;
        }
        float w = ex2(dot16v(qv, Ks4[key*4+0], Ks4[key*4+1], Ks4[key*4+2], Ks4[key*4+3]));
        accum(w, Vs4[key*4+0], Vs4[key*4+1], Vs4[key*4+2], Vs4[key*4+3], l, acc);
    }

    // ---- finalize ----
    if (valid) {
        float inv = 1.0f / l;
        float4* o = (float4*)(g_heads + ((size_t)hb*GG + n)*KDD);
#pragma unroll
        for (int t = 0; t < 4; t++)
            o[t] = make_float4(acc[t*4+0]*inv, acc[t*4+1]*inv, acc[t*4+2]*inv, acc[t*4+3]*inv);
    }
}

// ---------------------------------------------------------------------------
// Kernel 3: output projection. out[t,e] = sum_hk heads[t,hk]*Wout[hk,e]
// ---------------------------------------------------------------------------
__global__ void out_kernel(const float* __restrict__ Wout, float* __restrict__ out) {
    extern __shared__ float sm[];
    float* hs = sm;                  // 32 * 129
    float* ws = sm + 32*129;         // 128 * 128

    const int tid = threadIdx.x;
    const int t0  = blockIdx.x * 32;

    for (int i = tid; i < HH*KDD*EE; i += 128) ws[i] = Wout[i];
    for (int i = tid; i < 32*HH*KDD; i += 128) {
        int t = i >> 7, hk = i & 127;
        int tt = t0 + t;
        float v = 0.f;
        if (tt < NTOK)
            v = g_heads[((size_t)(hk >> 4)*NTOK + tt)*KDD + (hk & 15)];
        hs[t*129 + hk] = v;
    }
    __syncthreads();

    const int eg = tid & 15;
    const int tg = tid >> 4;
    float acc[4][8];
#pragma unroll
    for (int ti = 0; ti < 4; ti++)
#pragma unroll
        for (int ei = 0; ei < 8; ei++) acc[ti][ei] = 0.f;

#pragma unroll 4
    for (int hk = 0; hk < 128; hk++) {
        float w[8], hv[4];
#pragma unroll
        for (int ei = 0; ei < 8; ei++) w[ei] = ws[hk*128 + eg + 16*ei];
#pragma unroll
        for (int ti = 0; ti < 4; ti++) hv[ti] = hs[(tg*4 + ti)*129 + hk];
#pragma unroll
        for (int ti = 0; ti < 4; ti++)
#pragma unroll
            for (int ei = 0; ei < 8; ei++) acc[ti][ei] += hv[ti]*w[ei];
    }

#pragma unroll
    for (int ti = 0; ti < 4; ti++) {
        int tt = t0 + tg*4 + ti;
        if (tt < NTOK) {
#pragma unroll
            for (int ei = 0; ei < 8; ei++)
                out[(size_t)tt*EE + eg + 16*ei] = acc[ti][ei];
        }
    }
}

// ---------------------------------------------------------------------------
extern "C" void kernel_launch(void* const* d_in, const int* in_sizes, int n_in,
                              void* d_out, int out_size) {
    const float* q = (const float*)d_in[0];
    WArgs wa;
    for (int i = 0; i < 9; i++) wa.w[i] = (const float*)d_in[1 + i];
    const float* Wout = (const float*)d_in[10];
    float* out = (float*)d_out;

    const int projSmem = (64*132 + 128*64) * sizeof(float);    // 66560 B
    const int attnSmem = GG*KDD*2*sizeof(float);               // 64128 B
    const int outSmem  = (32*129 + 128*128) * sizeof(float);
    cudaFuncSetAttribute(proj_kernel, cudaFuncAttributeMaxDynamicSharedMemorySize, projSmem);
    cudaFuncSetAttribute(attn_kernel, cudaFuncAttributeMaxDynamicSharedMemorySize, attnSmem);
    cudaFuncSetAttribute(out_kernel,  cudaFuncAttributeMaxDynamicSharedMemorySize, outSmem);

    proj_kernel<<<dim3(756, 2), 256, projSmem>>>(q, wa);
    attn_kernel<<<dim3(HH*BB, 4), 128, attnSmem>>>();
    out_kernel<<<(NTOK + 31)/32, 128, outSmem>>>(Wout, out);
}

// round 7
// speedup vs baseline: 2.8636x; 1.4271x over previous
#include <cuda_runtime.h>

// ---------------------------------------------------------------------------
// Problem constants
// ---------------------------------------------------------------------------
#define HH   8
#define DD   128
#define KDD  16
#define EE   128
#define BB   16
#define GG   501
#define NPP  250
#define NTOK (BB*GG)      // 8016
#define NHALF (BB*NPP)    // 4000
#define SCALE2 0.3606737602222409f   // (1/sqrt(16)) * log2(e)

typedef unsigned long long ull;

// ---------------------------------------------------------------------------
// Scratch
// ---------------------------------------------------------------------------
__device__ float g_Q[HH*NTOK*KDD];
__device__ float g_K[HH*NTOK*KDD];
__device__ float g_V[HH*NTOK*KDD];
// [0]=W1(pick single) [1]=W2(pick vs K_pick) [2]=W3(pick vs K_del)
// [3]=W4(del single)  [4]=W5(del vs K_del)   [5]=W6(del vs K_pick)
__device__ float g_EQ[6][HH*NHALF*KDD];
__device__ float g_heads[HH*NTOK*KDD];

struct WArgs { const float* w[9]; };

// ---------------------------------------------------------------------------
// Packed fp32x2 helpers (FFMA2 path — ptxas never auto-fuses from C++)
// ---------------------------------------------------------------------------
__device__ __forceinline__ ull mul2(ull a, ull b) {
    ull r; asm("mul.rn.f32x2 %0,%1,%2;" : "=l"(r) : "l"(a), "l"(b)); return r;
}
__device__ __forceinline__ void fma2(ull& d, ull a, ull b) {
    asm("fma.rn.f32x2 %0,%1,%2,%0;" : "+l"(d) : "l"(a), "l"(b));
}
__device__ __forceinline__ ull add2(ull a, ull b) {
    ull r; asm("add.rn.f32x2 %0,%1,%2;" : "=l"(r) : "l"(a), "l"(b)); return r;
}
__device__ __forceinline__ ull pk2(float lo, float hi) {
    ull r; asm("mov.b64 %0,{%1,%2};" : "=l"(r) : "f"(lo), "f"(hi)); return r;
}
__device__ __forceinline__ float2 up2(ull a) {
    float lo, hi; asm("mov.b64 {%0,%1},%2;" : "=f"(lo), "=f"(hi) : "l"(a));
    return make_float2(lo, hi);
}
__device__ __forceinline__ float ex2(float x) {
    float r; asm("ex2.approx.f32 %0, %1;" : "=f"(r) : "f"(x)); return r;
}

// ---------------------------------------------------------------------------
// Kernel 1: projections as folded GEMMs (packed f32x2 inner loop).
// out[h,row,k] = sum_d q[row,d]*W[h,d,k]; (h,k)->col: [rows,128]x[128,128].
// 64 rows x 64 cols per block, 256 threads, 4 rows x 4 cols per thread.
// ---------------------------------------------------------------------------
__global__ void __launch_bounds__(256, 3) proj_kernel(const float* __restrict__ q, WArgs a) {
    extern __shared__ float sm[];
    float* qs = sm;              // 64 * 132 (padded)
    float* ws = sm + 64*132;     // 128 * 64

    int bx = blockIdx.x;
    const int ch = blockIdx.y;   // column half (0/1)
    int job, tile;
    if (bx < 378) { job = bx / 126; tile = bx % 126; }
    else          { bx -= 378; job = 3 + bx / 63; tile = bx % 63; }

    const bool full = (job < 3);
    const int nrows = full ? NTOK : NHALF;
    const int r0 = tile * 64;
    const int tid = threadIdx.x;

    // ---- weight tile (float4 loads) ----
    {
        const float4* W4 = (const float4*)a.w[job];
        float4* ws4 = (float4*)ws;
        for (int i = tid; i < DD*16; i += 256) {
            int d = i >> 4, c4 = i & 15;
            int gc4 = ch*16 + c4;
            ws4[i] = W4[(gc4 >> 2)*(DD*4) + d*4 + (gc4 & 3)];
        }
    }

    // ---- q tile ----
    const int off = full ? 0 : ((job < 6) ? 1 : (NPP + 1));
    float4* qs4 = (float4*)qs;
    for (int i = tid; i < 64*32; i += 256) {
        int lr = i >> 5, d4 = i & 31;
        int rt = r0 + lr;
        float4 v = make_float4(0.f, 0.f, 0.f, 0.f);
        if (rt < nrows) {
            size_t srow;
            if (full) srow = (size_t)rt;
            else {
                int b = rt / NPP, p = rt % NPP;
                srow = (size_t)(b*GG + off + p);
            }
            v = ((const float4*)q)[srow*32 + d4];
        }
        qs4[lr*33 + d4] = v;
    }
    __syncthreads();

    const int cg = tid & 15;
    const int rg = tid >> 4;
    const float* qrow = qs + rg*4*132;
    // 64 floats/row = 256B = 16 ulonglong2 per d-row
    const ulonglong2* wsU = (const ulonglong2*)ws;

    ull acc[4][2];
#pragma unroll
    for (int i = 0; i < 4; i++) { acc[i][0] = 0ull; acc[i][1] = 0ull; }

#pragma unroll 8
    for (int d = 0; d < DD; d++) {
        ulonglong2 w2 = wsU[d*16 + cg];
        ull qb[4];
#pragma unroll
        for (int ri = 0; ri < 4; ri++) {
            float qv = qrow[ri*132 + d];
            qb[ri] = pk2(qv, qv);
        }
#pragma unroll
        for (int ri = 0; ri < 4; ri++) {
            fma2(acc[ri][0], qb[ri], w2.x);
            fma2(acc[ri][1], qb[ri], w2.y);
        }
    }

    float* outp;
    if      (job == 0) outp = g_Q;
    else if (job == 1) outp = g_K;
    else if (job == 2) outp = g_V;
    else               outp = g_EQ[job-3];

    const int gcol0 = ch*64 + cg*4;
    const int h  = gcol0 >> 4;
    const int k0 = gcol0 & 15;
#pragma unroll
    for (int ri = 0; ri < 4; ri++) {
        int rt = r0 + rg*4 + ri;
        if (rt < nrows) {
            float2 a0 = up2(acc[ri][0]);
            float2 a1 = up2(acc[ri][1]);
            float* o = outp + ((size_t)h*nrows + rt)*KDD + k0;
            *(float4*)o = make_float4(a0.x, a0.y, a1.x, a1.y);
        }
    }
}

// ---------------------------------------------------------------------------
// Attention per-key body (packed). 19 fma-pipe instrs per (q,key) pair.
// Key row = 16 floats = 4 ulonglong2.
// ---------------------------------------------------------------------------
__device__ __forceinline__ void attn_key(const ulonglong2* KsU,
                                         const ulonglong2* VsU,
                                         int j, const ull* qp, bool active,
                                         float& l, ull* acc) {
    ulonglong2 ka = KsU[j*4+0], kb = KsU[j*4+1], kc = KsU[j*4+2], kd = KsU[j*4+3];
    ull p0 = mul2(qp[0], ka.x);
    ull p1 = mul2(qp[1], ka.y);
    fma2(p0, qp[2], kb.x); fma2(p1, qp[3], kb.y);
    fma2(p0, qp[4], kc.x); fma2(p1, qp[5], kc.y);
    fma2(p0, qp[6], kd.x); fma2(p1, qp[7], kd.y);
    float2 s = up2(add2(p0, p1));
    float w = active ? ex2(s.x + s.y) : 0.f;
    l += w;
    ull wp = pk2(w, w);
    ulonglong2 va = VsU[j*4+0], vb = VsU[j*4+1], vc = VsU[j*4+2], vd = VsU[j*4+3];
    fma2(acc[0], wp, va.x); fma2(acc[1], wp, va.y);
    fma2(acc[2], wp, vb.x); fma2(acc[3], wp, vb.y);
    fma2(acc[4], wp, vc.x); fma2(acc[5], wp, vc.y);
    fma2(acc[6], wp, vd.x); fma2(acc[7], wp, vd.y);
}

__device__ __forceinline__ void loadq(const float* src, ull* qp) {
    const float4* s4 = (const float4*)src;
#pragma unroll
    for (int t = 0; t < 4; t++) {
        float4 v = s4[t];
        qp[2*t]   = pk2(v.x*SCALE2, v.y*SCALE2);
        qp[2*t+1] = pk2(v.z*SCALE2, v.w*SCALE2);
    }
}

// ---------------------------------------------------------------------------
// Kernel 2: attention, one query per thread, packed f32x2 accumulation.
// grid (HB=128, 2 q-chunks of 256), block 256.
// ---------------------------------------------------------------------------
__global__ void __launch_bounds__(256, 3) attn_kernel() {
    extern __shared__ float sm[];
    const ulonglong2* KsU = (const ulonglong2*)sm;            // GG*4
    const ulonglong2* VsU = KsU + GG*4;

    const int hb  = blockIdx.x;
    const int tid = threadIdx.x;

    {
        const float4* K4 = (const float4*)(g_K + (size_t)hb * GG * KDD);
        const float4* V4 = (const float4*)(g_V + (size_t)hb * GG * KDD);
        float4* Ks4 = (float4*)sm;
        float4* Vs4 = Ks4 + GG*4;
        for (int i = tid; i < GG*4; i += 256) {
            Ks4[i] = K4[i];
            Vs4[i] = V4[i];
        }
    }
    __syncthreads();

    const int n = blockIdx.y * 256 + tid;
    const bool valid = (n < GG);
    const int nn = valid ? n : 0;

    ull qp[8], acc[8];
    float l = 0.f;
#pragma unroll
    for (int k = 0; k < 8; k++) acc[k] = 0ull;
    loadq(g_Q + ((size_t)hb*GG + nn)*KDD, qp);

    // ---- base: all G keys ----
#pragma unroll 2
    for (int j = 0; j < GG; j++)
        attn_key(KsU, VsU, j, qp, true, l, acc);

    const bool pk = (n >= 1) && (n <= NPP);
    const bool dl = (n >= NPP+1) && (n < GG);
    const bool ex = pk || dl;
    const int  p  = pk ? (n-1) : (n-NPP-1);

    // ---- extras A: pick keys 1..NPP; pick q -> EQ1 (W2), del q -> EQ5 (W6) ----
    if (ex) loadq((pk ? g_EQ[1] : g_EQ[5]) + ((size_t)hb*NPP + p)*KDD, qp);
#pragma unroll 2
    for (int j = 1; j <= NPP; j++)
        attn_key(KsU, VsU, j, qp, ex, l, acc);

    // ---- extras B: del keys NPP+1..2NPP; pick q -> EQ2 (W3), del q -> EQ4 (W5) ----
    if (ex) loadq((pk ? g_EQ[2] : g_EQ[4]) + ((size_t)hb*NPP + p)*KDD, qp);
#pragma unroll 2
    for (int j = NPP+1; j <= 2*NPP; j++)
        attn_key(KsU, VsU, j, qp, ex, l, acc);

    // ---- single paired extra: pick q -> K_del[p] (EQ0/W1), del q -> K_pick[p] (EQ3/W4) ----
    if (ex) {
        const int key = pk ? (NPP+1+p) : (1+p);
        loadq((pk ? g_EQ[0] : g_EQ[3]) + ((size_t)hb*NPP + p)*KDD, qp);
        attn_key(KsU, VsU, key, qp, true, l, acc);
    }

    // ---- finalize ----
    if (valid) {
        float inv = 1.0f / l;
        float4* o = (float4*)(g_heads + ((size_t)hb*GG + n)*KDD);
#pragma unroll
        for (int t = 0; t < 4; t++) {
            float2 a0 = up2(acc[2*t]);
            float2 a1 = up2(acc[2*t+1]);
            o[t] = make_float4(a0.x*inv, a0.y*inv, a1.x*inv, a1.y*inv);
        }
    }
}

// ---------------------------------------------------------------------------
// Kernel 3: output projection (packed). out[t,e] = sum_hk heads[t,hk]*Wout[hk,e]
// ws rows: 128 floats = 512B = 32 ulonglong2 per hk-row (stride 32 — the R5 bug
// used 16 and scrambled the output).
// ---------------------------------------------------------------------------
__global__ void out_kernel(const float* __restrict__ Wout, float* __restrict__ out) {
    extern __shared__ float sm[];
    float* hs = sm;                  // 32 * 129
    float* ws = sm + 32*129;         // 128 * 128

    const int tid = threadIdx.x;
    const int t0  = blockIdx.x * 32;

    for (int i = tid; i < HH*KDD*EE; i += 128) ws[i] = Wout[i];
    for (int i = tid; i < 32*HH*KDD; i += 128) {
        int t = i >> 7, hk = i & 127;
        int tt = t0 + t;
        float v = 0.f;
        if (tt < NTOK)
            v = g_heads[((size_t)(hk >> 4)*NTOK + tt)*KDD + (hk & 15)];
        hs[t*129 + hk] = v;
    }
    __syncthreads();

    const int eg = tid & 15;         // cols eg*8 .. eg*8+7
    const int tg = tid >> 4;
    const ulonglong2* wsU = (const ulonglong2*)ws;   // 32 per hk-row

    ull acc[4][4];
#pragma unroll
    for (int ti = 0; ti < 4; ti++)
#pragma unroll
        for (int c = 0; c < 4; c++) acc[ti][c] = 0ull;

#pragma unroll 4
    for (int hk = 0; hk < 128; hk++) {
        ulonglong2 wa = wsU[hk*32 + eg*2];
        ulonglong2 wb = wsU[hk*32 + eg*2 + 1];
        ull hb[4];
#pragma unroll
        for (int ti = 0; ti < 4; ti++) {
            float hv = hs[(tg*4 + ti)*129 + hk];
            hb[ti] = pk2(hv, hv);
        }
#pragma unroll
        for (int ti = 0; ti < 4; ti++) {
            fma2(acc[ti][0], hb[ti], wa.x);
            fma2(acc[ti][1], hb[ti], wa.y);
            fma2(acc[ti][2], hb[ti], wb.x);
            fma2(acc[ti][3], hb[ti], wb.y);
        }
    }

#pragma unroll
    for (int ti = 0; ti < 4; ti++) {
        int tt = t0 + tg*4 + ti;
        if (tt < NTOK) {
            float2 a0 = up2(acc[ti][0]), a1 = up2(acc[ti][1]);
            float2 a2 = up2(acc[ti][2]), a3 = up2(acc[ti][3]);
            float* o = out + (size_t)tt*EE + eg*8;
            *(float4*)(o)     = make_float4(a0.x, a0.y, a1.x, a1.y);
            *(float4*)(o + 4) = make_float4(a2.x, a2.y, a3.x, a3.y);
        }
    }
}

// ---------------------------------------------------------------------------
extern "C" void kernel_launch(void* const* d_in, const int* in_sizes, int n_in,
                              void* d_out, int out_size) {
    const float* q = (const float*)d_in[0];
    WArgs wa;
    for (int i = 0; i < 9; i++) wa.w[i] = (const float*)d_in[1 + i];
    const float* Wout = (const float*)d_in[10];
    float* out = (float*)d_out;

    const int projSmem = (64*132 + 128*64) * sizeof(float);    // 66560 B
    const int attnSmem = GG*KDD*2*sizeof(float);               // 64128 B
    const int outSmem  = (32*129 + 128*128) * sizeof(float);
    cudaFuncSetAttribute(proj_kernel, cudaFuncAttributeMaxDynamicSharedMemorySize, projSmem);
    cudaFuncSetAttribute(attn_kernel, cudaFuncAttributeMaxDynamicSharedMemorySize, attnSmem);
    cudaFuncSetAttribute(out_kernel,  cudaFuncAttributeMaxDynamicSharedMemorySize, outSmem);

    proj_kernel<<<dim3(756, 2), 256, projSmem>>>(q, wa);
    attn_kernel<<<dim3(HH*BB, 2), 256, attnSmem>>>();
    out_kernel<<<(NTOK + 31)/32, 128, outSmem>>>(Wout, out);
}

// round 8
// speedup vs baseline: 3.0525x; 1.0660x over previous
#include <cuda_runtime.h>

// ---------------------------------------------------------------------------
// Problem constants
// ---------------------------------------------------------------------------
#define HH   8
#define DD   128
#define KDD  16
#define EE   128
#define BB   16
#define GG   501
#define NPP  250
#define NTOK (BB*GG)      // 8016
#define NHALF (BB*NPP)    // 4000
#define SCALE2 0.3606737602222409f   // (1/sqrt(16)) * log2(e)

typedef unsigned long long ull;

// ---------------------------------------------------------------------------
// Scratch
// ---------------------------------------------------------------------------
__device__ float g_Q[HH*NTOK*KDD];
__device__ float g_K[HH*NTOK*KDD];
__device__ float g_V[HH*NTOK*KDD];
// [0]=W1(pick single) [1]=W2(pick vs K_pick) [2]=W3(pick vs K_del)
// [3]=W4(del single)  [4]=W5(del vs K_del)   [5]=W6(del vs K_pick)
__device__ float g_EQ[6][HH*NHALF*KDD];
__device__ float g_heads[HH*NTOK*KDD];

struct WArgs { const float* w[9]; };

// ---------------------------------------------------------------------------
// Packed fp32x2 helpers
// ---------------------------------------------------------------------------
__device__ __forceinline__ ull mul2(ull a, ull b) {
    ull r; asm("mul.rn.f32x2 %0,%1,%2;" : "=l"(r) : "l"(a), "l"(b)); return r;
}
__device__ __forceinline__ void fma2(ull& d, ull a, ull b) {
    asm("fma.rn.f32x2 %0,%1,%2,%0;" : "+l"(d) : "l"(a), "l"(b));
}
__device__ __forceinline__ ull add2(ull a, ull b) {
    ull r; asm("add.rn.f32x2 %0,%1,%2;" : "=l"(r) : "l"(a), "l"(b)); return r;
}
__device__ __forceinline__ ull pk2(float lo, float hi) {
    ull r; asm("mov.b64 %0,{%1,%2};" : "=l"(r) : "f"(lo), "f"(hi)); return r;
}
__device__ __forceinline__ float2 up2(ull a) {
    float lo, hi; asm("mov.b64 {%0,%1},%2;" : "=f"(lo), "=f"(hi) : "l"(a));
    return make_float2(lo, hi);
}
__device__ __forceinline__ float ex2(float x) {
    float r; asm("ex2.approx.f32 %0, %1;" : "=f"(r) : "f"(x)); return r;
}

// ---------------------------------------------------------------------------
// Kernel 1: projections as folded GEMMs (packed math, vectorized q loads).
// 64 rows x 64 cols per block, 256 threads, 4 rows x 4 cols per thread.
// ---------------------------------------------------------------------------
__global__ void __launch_bounds__(256, 3) proj_kernel(const float* __restrict__ q, WArgs a) {
    extern __shared__ float sm[];
    float* qs = sm;              // 64 * 132 (padded; 132%4==0 -> float4-aligned rows)
    float* ws = sm + 64*132;     // 128 * 64

    int bx = blockIdx.x;
    const int ch = blockIdx.y;   // column half (0/1)
    int job, tile;
    if (bx < 378) { job = bx / 126; tile = bx % 126; }
    else          { bx -= 378; job = 3 + bx / 63; tile = bx % 63; }

    const bool full = (job < 3);
    const int nrows = full ? NTOK : NHALF;
    const int r0 = tile * 64;
    const int tid = threadIdx.x;

    // ---- weight tile (float4 loads) ----
    {
        const float4* W4 = (const float4*)a.w[job];
        float4* ws4 = (float4*)ws;
        for (int i = tid; i < DD*16; i += 256) {
            int d = i >> 4, c4 = i & 15;
            int gc4 = ch*16 + c4;
            ws4[i] = W4[(gc4 >> 2)*(DD*4) + d*4 + (gc4 & 3)];
        }
    }

    // ---- q tile ----
    const int off = full ? 0 : ((job < 6) ? 1 : (NPP + 1));
    float4* qs4 = (float4*)qs;
    for (int i = tid; i < 64*32; i += 256) {
        int lr = i >> 5, d4 = i & 31;
        int rt = r0 + lr;
        float4 v = make_float4(0.f, 0.f, 0.f, 0.f);
        if (rt < nrows) {
            size_t srow;
            if (full) srow = (size_t)rt;
            else {
                int b = rt / NPP, p = rt % NPP;
                srow = (size_t)(b*GG + off + p);
            }
            v = ((const float4*)q)[srow*32 + d4];
        }
        qs4[lr*33 + d4] = v;
    }
    __syncthreads();

    const int cg = tid & 15;
    const int rg = tid >> 4;
    const float* qrow = qs + rg*4*132;
    const ulonglong2* wsU = (const ulonglong2*)ws;   // 16 ulonglong2 per d-row

    ull acc[4][2];
#pragma unroll
    for (int i = 0; i < 4; i++) { acc[i][0] = 0ull; acc[i][1] = 0ull; }

#pragma unroll 2
    for (int d4 = 0; d4 < 32; d4++) {       // d = d4*4 .. d4*4+3
        float4 qv[4];
#pragma unroll
        for (int ri = 0; ri < 4; ri++)
            qv[ri] = *(const float4*)(qrow + ri*132 + d4*4);
        ulonglong2 w0 = wsU[(d4*4+0)*16 + cg];
        ulonglong2 w1 = wsU[(d4*4+1)*16 + cg];
        ulonglong2 w2 = wsU[(d4*4+2)*16 + cg];
        ulonglong2 w3 = wsU[(d4*4+3)*16 + cg];
#pragma unroll
        for (int ri = 0; ri < 4; ri++) {
            ull b0 = pk2(qv[ri].x, qv[ri].x);
            ull b1 = pk2(qv[ri].y, qv[ri].y);
            ull b2 = pk2(qv[ri].z, qv[ri].z);
            ull b3 = pk2(qv[ri].w, qv[ri].w);
            fma2(acc[ri][0], b0, w0.x); fma2(acc[ri][1], b0, w0.y);
            fma2(acc[ri][0], b1, w1.x); fma2(acc[ri][1], b1, w1.y);
            fma2(acc[ri][0], b2, w2.x); fma2(acc[ri][1], b2, w2.y);
            fma2(acc[ri][0], b3, w3.x); fma2(acc[ri][1], b3, w3.y);
        }
    }

    float* outp;
    if      (job == 0) outp = g_Q;
    else if (job == 1) outp = g_K;
    else if (job == 2) outp = g_V;
    else               outp = g_EQ[job-3];

    const int gcol0 = ch*64 + cg*4;
    const int h  = gcol0 >> 4;
    const int k0 = gcol0 & 15;
#pragma unroll
    for (int ri = 0; ri < 4; ri++) {
        int rt = r0 + rg*4 + ri;
        if (rt < nrows) {
            float2 a0 = up2(acc[ri][0]);
            float2 a1 = up2(acc[ri][1]);
            float* o = outp + ((size_t)h*nrows + rt)*KDD + k0;
            *(float4*)o = make_float4(a0.x, a0.y, a1.x, a1.y);
        }
    }
}

// ---------------------------------------------------------------------------
// Attention: 2 queries per thread. K/V row = 16 floats = 4 ulonglong2.
// ---------------------------------------------------------------------------
__device__ __forceinline__ float dotp(const ull* qp,
        ulonglong2 ka, ulonglong2 kb, ulonglong2 kc, ulonglong2 kd) {
    ull p0 = mul2(qp[0], ka.x);
    ull p1 = mul2(qp[1], ka.y);
    fma2(p0, qp[2], kb.x); fma2(p1, qp[3], kb.y);
    fma2(p0, qp[4], kc.x); fma2(p1, qp[5], kc.y);
    fma2(p0, qp[6], kd.x); fma2(p1, qp[7], kd.y);
    float2 s = up2(add2(p0, p1));
    return s.x + s.y;
}

__device__ __forceinline__ void accum(float w, ull* acc, float& l,
        ulonglong2 va, ulonglong2 vb, ulonglong2 vc, ulonglong2 vd) {
    l += w;
    ull wp = pk2(w, w);
    fma2(acc[0], wp, va.x); fma2(acc[1], wp, va.y);
    fma2(acc[2], wp, vb.x); fma2(acc[3], wp, vb.y);
    fma2(acc[4], wp, vc.x); fma2(acc[5], wp, vc.y);
    fma2(acc[6], wp, vd.x); fma2(acc[7], wp, vd.y);
}

__device__ __forceinline__ void attn_key2(const ulonglong2* KsU, const ulonglong2* VsU,
        int j,
        const ull* qp0, bool a0, float& l0, ull* acc0,
        const ull* qp1, bool a1, float& l1, ull* acc1) {
    ulonglong2 ka = KsU[j*4+0], kb = KsU[j*4+1], kc = KsU[j*4+2], kd = KsU[j*4+3];
    float s0 = dotp(qp0, ka, kb, kc, kd);
    float s1 = dotp(qp1, ka, kb, kc, kd);
    float w0 = a0 ? ex2(s0) : 0.f;
    float w1 = a1 ? ex2(s1) : 0.f;
    ulonglong2 va = VsU[j*4+0], vb = VsU[j*4+1], vc = VsU[j*4+2], vd = VsU[j*4+3];
    accum(w0, acc0, l0, va, vb, vc, vd);
    accum(w1, acc1, l1, va, vb, vc, vd);
}

__device__ __forceinline__ void loadq(const float* src, ull* qp) {
    const float4* s4 = (const float4*)src;
#pragma unroll
    for (int t = 0; t < 4; t++) {
        float4 v = s4[t];
        qp[2*t]   = pk2(v.x*SCALE2, v.y*SCALE2);
        qp[2*t+1] = pk2(v.z*SCALE2, v.w*SCALE2);
    }
}

// ---------------------------------------------------------------------------
// Kernel 2: attention, 2 queries/thread, packed f32x2.
// grid (HB=128, 2 chunks of 256 queries), block 128.
// Thread t: queries base+t and base+128+t.
// ---------------------------------------------------------------------------
__global__ void __launch_bounds__(128, 3) attn_kernel() {
    extern __shared__ float sm[];
    const ulonglong2* KsU = (const ulonglong2*)sm;            // GG*4
    const ulonglong2* VsU = KsU + GG*4;

    const int hb  = blockIdx.x;
    const int tid = threadIdx.x;

    {
        const float4* K4 = (const float4*)(g_K + (size_t)hb * GG * KDD);
        const float4* V4 = (const float4*)(g_V + (size_t)hb * GG * KDD);
        float4* Ks4 = (float4*)sm;
        float4* Vs4 = Ks4 + GG*4;
        for (int i = tid; i < GG*4; i += 128) {
            Ks4[i] = K4[i];
            Vs4[i] = V4[i];
        }
    }
    __syncthreads();

    const int base = blockIdx.y * 256;
    const int n0 = base + tid;
    const int n1 = base + 128 + tid;
    const bool v0 = (n0 < GG);
    const bool v1 = (n1 < GG);
    const int nn0 = v0 ? n0 : 0;
    const int nn1 = v1 ? n1 : 0;

    ull qp0[8], qp1[8], acc0[8], acc1[8];
    float l0 = 0.f, l1 = 0.f;
#pragma unroll
    for (int k = 0; k < 8; k++) { acc0[k] = 0ull; acc1[k] = 0ull; }
    loadq(g_Q + ((size_t)hb*GG + nn0)*KDD, qp0);
    loadq(g_Q + ((size_t)hb*GG + nn1)*KDD, qp1);

    // ---- base: all G keys ----
    for (int j = 0; j < GG; j++)
        attn_key2(KsU, VsU, j, qp0, true, l0, acc0, qp1, true, l1, acc1);

    const bool pk0 = (n0 >= 1) && (n0 <= NPP);
    const bool dl0 = (n0 >= NPP+1) && (n0 < GG);
    const bool ex0 = pk0 || dl0;
    const int  p0  = pk0 ? (n0-1) : (n0-NPP-1);
    const bool pk1 = (n1 >= 1) && (n1 <= NPP);
    const bool dl1 = (n1 >= NPP+1) && (n1 < GG);
    const bool ex1 = pk1 || dl1;
    const int  p1  = pk1 ? (n1-1) : (n1-NPP-1);

    // ---- extras A: pick keys 1..NPP; pick q -> EQ1 (W2), del q -> EQ5 (W6) ----
    if (ex0) loadq((pk0 ? g_EQ[1] : g_EQ[5]) + ((size_t)hb*NPP + p0)*KDD, qp0);
    if (ex1) loadq((pk1 ? g_EQ[1] : g_EQ[5]) + ((size_t)hb*NPP + p1)*KDD, qp1);
    for (int j = 1; j <= NPP; j++)
        attn_key2(KsU, VsU, j, qp0, ex0, l0, acc0, qp1, ex1, l1, acc1);

    // ---- extras B: del keys NPP+1..2NPP; pick q -> EQ2 (W3), del q -> EQ4 (W5) ----
    if (ex0) loadq((pk0 ? g_EQ[2] : g_EQ[4]) + ((size_t)hb*NPP + p0)*KDD, qp0);
    if (ex1) loadq((pk1 ? g_EQ[2] : g_EQ[4]) + ((size_t)hb*NPP + p1)*KDD, qp1);
    for (int j = NPP+1; j <= 2*NPP; j++)
        attn_key2(KsU, VsU, j, qp0, ex0, l0, acc0, qp1, ex1, l1, acc1);

    // ---- single paired extras ----
    if (ex0) {
        const int key = pk0 ? (NPP+1+p0) : (1+p0);
        loadq((pk0 ? g_EQ[0] : g_EQ[3]) + ((size_t)hb*NPP + p0)*KDD, qp0);
        ulonglong2 ka = KsU[key*4+0], kb = KsU[key*4+1], kc = KsU[key*4+2], kd = KsU[key*4+3];
        float w = ex2(dotp(qp0, ka, kb, kc, kd));
        accum(w, acc0, l0, VsU[key*4+0], VsU[key*4+1], VsU[key*4+2], VsU[key*4+3]);
    }
    if (ex1) {
        const int key = pk1 ? (NPP+1+p1) : (1+p1);
        loadq((pk1 ? g_EQ[0] : g_EQ[3]) + ((size_t)hb*NPP + p1)*KDD, qp1);
        ulonglong2 ka = KsU[key*4+0], kb = KsU[key*4+1], kc = KsU[key*4+2], kd = KsU[key*4+3];
        float w = ex2(dotp(qp1, ka, kb, kc, kd));
        accum(w, acc1, l1, VsU[key*4+0], VsU[key*4+1], VsU[key*4+2], VsU[key*4+3]);
    }

    // ---- finalize ----
    if (v0) {
        float inv = 1.0f / l0;
        float4* o = (float4*)(g_heads + ((size_t)hb*GG + n0)*KDD);
#pragma unroll
        for (int t = 0; t < 4; t++) {
            float2 a0 = up2(acc0[2*t]);
            float2 a1 = up2(acc0[2*t+1]);
            o[t] = make_float4(a0.x*inv, a0.y*inv, a1.x*inv, a1.y*inv);
        }
    }
    if (v1) {
        float inv = 1.0f / l1;
        float4* o = (float4*)(g_heads + ((size_t)hb*GG + n1)*KDD);
#pragma unroll
        for (int t = 0; t < 4; t++) {
            float2 a0 = up2(acc1[2*t]);
            float2 a1 = up2(acc1[2*t+1]);
            o[t] = make_float4(a0.x*inv, a0.y*inv, a1.x*inv, a1.y*inv);
        }
    }
}

// ---------------------------------------------------------------------------
// Kernel 3: output projection (packed). ws row = 128 floats = 32 ulonglong2.
// ---------------------------------------------------------------------------
__global__ void out_kernel(const float* __restrict__ Wout, float* __restrict__ out) {
    extern __shared__ float sm[];
    float* hs = sm;                  // 32 * 129
    float* ws = sm + 32*129;         // 128 * 128

    const int tid = threadIdx.x;
    const int t0  = blockIdx.x * 32;

    for (int i = tid; i < HH*KDD*EE; i += 128) ws[i] = Wout[i];
    for (int i = tid; i < 32*HH*KDD; i += 128) {
        int t = i >> 7, hk = i & 127;
        int tt = t0 + t;
        float v = 0.f;
        if (tt < NTOK)
            v = g_heads[((size_t)(hk >> 4)*NTOK + tt)*KDD + (hk & 15)];
        hs[t*129 + hk] = v;
    }
    __syncthreads();

    const int eg = tid & 15;         // cols eg*8 .. eg*8+7
    const int tg = tid >> 4;
    const ulonglong2* wsU = (const ulonglong2*)ws;   // 32 per hk-row

    ull acc[4][4];
#pragma unroll
    for (int ti = 0; ti < 4; ti++)
#pragma unroll
        for (int c = 0; c < 4; c++) acc[ti][c] = 0ull;

#pragma unroll 4
    for (int hk = 0; hk < 128; hk++) {
        ulonglong2 wa = wsU[hk*32 + eg*2];
        ulonglong2 wb = wsU[hk*32 + eg*2 + 1];
        ull hb[4];
#pragma unroll
        for (int ti = 0; ti < 4; ti++) {
            float hv = hs[(tg*4 + ti)*129 + hk];
            hb[ti] = pk2(hv, hv);
        }
#pragma unroll
        for (int ti = 0; ti < 4; ti++) {
            fma2(acc[ti][0], hb[ti], wa.x);
            fma2(acc[ti][1], hb[ti], wa.y);
            fma2(acc[ti][2], hb[ti], wb.x);
            fma2(acc[ti][3], hb[ti], wb.y);
        }
    }

#pragma unroll
    for (int ti = 0; ti < 4; ti++) {
        int tt = t0 + tg*4 + ti;
        if (tt < NTOK) {
            float2 a0 = up2(acc[ti][0]), a1 = up2(acc[ti][1]);
            float2 a2 = up2(acc[ti][2]), a3 = up2(acc[ti][3]);
            float* o = out + (size_t)tt*EE + eg*8;
            *(float4*)(o)     = make_float4(a0.x, a0.y, a1.x, a1.y);
            *(float4*)(o + 4) = make_float4(a2.x, a2.y, a3.x, a3.y);
        }
    }
}

// ---------------------------------------------------------------------------
extern "C" void kernel_launch(void* const* d_in, const int* in_sizes, int n_in,
                              void* d_out, int out_size) {
    const float* q = (const float*)d_in[0];
    WArgs wa;
    for (int i = 0; i < 9; i++) wa.w[i] = (const float*)d_in[1 + i];
    const float* Wout = (const float*)d_in[10];
    float* out = (float*)d_out;

    const int projSmem = (64*132 + 128*64) * sizeof(float);    // 66560 B
    const int attnSmem = GG*KDD*2*sizeof(float);               // 64128 B
    const int outSmem  = (32*129 + 128*128) * sizeof(float);
    cudaFuncSetAttribute(proj_kernel, cudaFuncAttributeMaxDynamicSharedMemorySize, projSmem);
    cudaFuncSetAttribute(attn_kernel, cudaFuncAttributeMaxDynamicSharedMemorySize, attnSmem);
    cudaFuncSetAttribute(out_kernel,  cudaFuncAttributeMaxDynamicSharedMemorySize, outSmem);

    proj_kernel<<<dim3(756, 2), 256, projSmem>>>(q, wa);
    attn_kernel<<<dim3(HH*BB, 2), 128, attnSmem>>>();
    out_kernel<<<(NTOK + 31)/32, 128, outSmem>>>(Wout, out);
}

// round 9
// speedup vs baseline: 3.2792x; 1.0743x over previous
#include <cuda_runtime.h>

// ---------------------------------------------------------------------------
// Problem constants
// ---------------------------------------------------------------------------
#define HH   8
#define DD   128
#define KDD  16
#define EE   128
#define BB   16
#define GG   501
#define NPP  250
#define NTOK (BB*GG)      // 8016
#define NHALF (BB*NPP)    // 4000
#define SCALE2 0.3606737602222409f   // (1/sqrt(16)) * log2(e)

typedef unsigned long long ull;

// ---------------------------------------------------------------------------
// Scratch
// ---------------------------------------------------------------------------
__device__ float g_Q[HH*NTOK*KDD];
__device__ float g_K[HH*NTOK*KDD];
__device__ float g_V[HH*NTOK*KDD];
// [0]=W1(pick single) [1]=W2(pick vs K_pick) [2]=W3(pick vs K_del)
// [3]=W4(del single)  [4]=W5(del vs K_del)   [5]=W6(del vs K_pick)
__device__ float g_EQ[6][HH*NHALF*KDD];
__device__ float g_pacc[2][HH*NTOK*KDD];   // partial sum(w*V) per key-half
__device__ float g_pl[2][HH*NTOK];         // partial sum(w)   per key-half

struct WArgs { const float* w[9]; };

// ---------------------------------------------------------------------------
// Packed fp32x2 helpers
// ---------------------------------------------------------------------------
__device__ __forceinline__ ull mul2(ull a, ull b) {
    ull r; asm("mul.rn.f32x2 %0,%1,%2;" : "=l"(r) : "l"(a), "l"(b)); return r;
}
__device__ __forceinline__ void fma2(ull& d, ull a, ull b) {
    asm("fma.rn.f32x2 %0,%1,%2,%0;" : "+l"(d) : "l"(a), "l"(b));
}
__device__ __forceinline__ ull add2(ull a, ull b) {
    ull r; asm("add.rn.f32x2 %0,%1,%2;" : "=l"(r) : "l"(a), "l"(b)); return r;
}
__device__ __forceinline__ ull pk2(float lo, float hi) {
    ull r; asm("mov.b64 %0,{%1,%2};" : "=l"(r) : "f"(lo), "f"(hi)); return r;
}
__device__ __forceinline__ float2 up2(ull a) {
    float lo, hi; asm("mov.b64 {%0,%1},%2;" : "=f"(lo), "=f"(hi) : "l"(a));
    return make_float2(lo, hi);
}
__device__ __forceinline__ float ex2(float x) {
    float r; asm("ex2.approx.f32 %0, %1;" : "=f"(r) : "f"(x)); return r;
}

// ---------------------------------------------------------------------------
// Kernel 1: projections as folded GEMMs (packed f32x2).
// 64 rows x 64 cols per block, 256 threads, 4x4 per thread.
// ---------------------------------------------------------------------------
__global__ void __launch_bounds__(256, 3) proj_kernel(const float* __restrict__ q, WArgs a) {
    extern __shared__ float sm[];
    float* qs = sm;              // 64 * 132 (padded)
    float* ws = sm + 64*132;     // 128 * 64

    int bx = blockIdx.x;
    const int ch = blockIdx.y;   // column half (0/1)
    int job, tile;
    if (bx < 378) { job = bx / 126; tile = bx % 126; }
    else          { bx -= 378; job = 3 + bx / 63; tile = bx % 63; }

    const bool full = (job < 3);
    const int nrows = full ? NTOK : NHALF;
    const int r0 = tile * 64;
    const int tid = threadIdx.x;

    {
        const float4* W4 = (const float4*)a.w[job];
        float4* ws4 = (float4*)ws;
        for (int i = tid; i < DD*16; i += 256) {
            int d = i >> 4, c4 = i & 15;
            int gc4 = ch*16 + c4;
            ws4[i] = W4[(gc4 >> 2)*(DD*4) + d*4 + (gc4 & 3)];
        }
    }

    const int off = full ? 0 : ((job < 6) ? 1 : (NPP + 1));
    float4* qs4 = (float4*)qs;
    for (int i = tid; i < 64*32; i += 256) {
        int lr = i >> 5, d4 = i & 31;
        int rt = r0 + lr;
        float4 v = make_float4(0.f, 0.f, 0.f, 0.f);
        if (rt < nrows) {
            size_t srow;
            if (full) srow = (size_t)rt;
            else {
                int b = rt / NPP, p = rt % NPP;
                srow = (size_t)(b*GG + off + p);
            }
            v = ((const float4*)q)[srow*32 + d4];
        }
        qs4[lr*33 + d4] = v;
    }
    __syncthreads();

    const int cg = tid & 15;
    const int rg = tid >> 4;
    const float* qrow = qs + rg*4*132;
    const ulonglong2* wsU = (const ulonglong2*)ws;   // 16 per d-row

    ull acc[4][2];
#pragma unroll
    for (int i = 0; i < 4; i++) { acc[i][0] = 0ull; acc[i][1] = 0ull; }

#pragma unroll 2
    for (int d4 = 0; d4 < 32; d4++) {
        float4 qv[4];
#pragma unroll
        for (int ri = 0; ri < 4; ri++)
            qv[ri] = *(const float4*)(qrow + ri*132 + d4*4);
        ulonglong2 w0 = wsU[(d4*4+0)*16 + cg];
        ulonglong2 w1 = wsU[(d4*4+1)*16 + cg];
        ulonglong2 w2 = wsU[(d4*4+2)*16 + cg];
        ulonglong2 w3 = wsU[(d4*4+3)*16 + cg];
#pragma unroll
        for (int ri = 0; ri < 4; ri++) {
            ull b0 = pk2(qv[ri].x, qv[ri].x);
            ull b1 = pk2(qv[ri].y, qv[ri].y);
            ull b2 = pk2(qv[ri].z, qv[ri].z);
            ull b3 = pk2(qv[ri].w, qv[ri].w);
            fma2(acc[ri][0], b0, w0.x); fma2(acc[ri][1], b0, w0.y);
            fma2(acc[ri][0], b1, w1.x); fma2(acc[ri][1], b1, w1.y);
            fma2(acc[ri][0], b2, w2.x); fma2(acc[ri][1], b2, w2.y);
            fma2(acc[ri][0], b3, w3.x); fma2(acc[ri][1], b3, w3.y);
        }
    }

    float* outp;
    if      (job == 0) outp = g_Q;
    else if (job == 1) outp = g_K;
    else if (job == 2) outp = g_V;
    else               outp = g_EQ[job-3];

    const int gcol0 = ch*64 + cg*4;
    const int h  = gcol0 >> 4;
    const int k0 = gcol0 & 15;
#pragma unroll
    for (int ri = 0; ri < 4; ri++) {
        int rt = r0 + rg*4 + ri;
        if (rt < nrows) {
            float2 a0 = up2(acc[ri][0]);
            float2 a1 = up2(acc[ri][1]);
            float* o = outp + ((size_t)h*nrows + rt)*KDD + k0;
            *(float4*)o = make_float4(a0.x, a0.y, a1.x, a1.y);
        }
    }
}

// ---------------------------------------------------------------------------
// Attention helpers. K/V row = 16 floats = 4 ulonglong2.
// ---------------------------------------------------------------------------
__device__ __forceinline__ float dotp(const ull* qp,
        ulonglong2 ka, ulonglong2 kb, ulonglong2 kc, ulonglong2 kd) {
    ull p0 = mul2(qp[0], ka.x);
    ull p1 = mul2(qp[1], ka.y);
    fma2(p0, qp[2], kb.x); fma2(p1, qp[3], kb.y);
    fma2(p0, qp[4], kc.x); fma2(p1, qp[5], kc.y);
    fma2(p0, qp[6], kd.x); fma2(p1, qp[7], kd.y);
    float2 s = up2(add2(p0, p1));
    return s.x + s.y;
}

__device__ __forceinline__ void accum(float w, ull* acc, float& l,
        ulonglong2 va, ulonglong2 vb, ulonglong2 vc, ulonglong2 vd) {
    l += w;
    ull wp = pk2(w, w);
    fma2(acc[0], wp, va.x); fma2(acc[1], wp, va.y);
    fma2(acc[2], wp, vb.x); fma2(acc[3], wp, vb.y);
    fma2(acc[4], wp, vc.x); fma2(acc[5], wp, vc.y);
    fma2(acc[6], wp, vd.x); fma2(acc[7], wp, vd.y);
}

__device__ __forceinline__ void attn_key2(const ulonglong2* KsU, const ulonglong2* VsU,
        int j,
        const ull* qp0, bool a0, float& l0, ull* acc0,
        const ull* qp1, bool a1, float& l1, ull* acc1) {
    ulonglong2 ka = KsU[j*4+0], kb = KsU[j*4+1], kc = KsU[j*4+2], kd = KsU[j*4+3];
    float s0 = dotp(qp0, ka, kb, kc, kd);
    float s1 = dotp(qp1, ka, kb, kc, kd);
    float w0 = a0 ? ex2(s0) : 0.f;
    float w1 = a1 ? ex2(s1) : 0.f;
    ulonglong2 va = VsU[j*4+0], vb = VsU[j*4+1], vc = VsU[j*4+2], vd = VsU[j*4+3];
    accum(w0, acc0, l0, va, vb, vc, vd);
    accum(w1, acc1, l1, va, vb, vc, vd);
}

__device__ __forceinline__ void loadq(const float* src, ull* qp) {
    const float4* s4 = (const float4*)src;
#pragma unroll
    for (int t = 0; t < 4; t++) {
        float4 v = s4[t];
        qp[2*t]   = pk2(v.x*SCALE2, v.y*SCALE2);
        qp[2*t+1] = pk2(v.z*SCALE2, v.w*SCALE2);
    }
}

// ---------------------------------------------------------------------------
// Kernel 2: attention split over keys. grid (HB=128, 2 qchunks, 2 keyhalves),
// block 128, 2 queries/thread. Partials (sum wV, sum w) -> g_pacc/g_pl.
//  z=0: base keys [0,251) + extras-A(pick keys, local 1..250) + del-paired
//  z=1: base keys [251,501) (local 0..249) + extras-B(del keys) + pick-paired
// ---------------------------------------------------------------------------
__global__ void __launch_bounds__(128, 3) attn_kernel() {
    extern __shared__ float sm[];
    const ulonglong2* KsU = (const ulonglong2*)sm;        // 251 rows * 4
    const ulonglong2* VsU = KsU + 251*4;

    const int hb  = blockIdx.x;
    const int tid = threadIdx.x;
    const int z   = blockIdx.z;
    const int nkeys = z ? 250 : 251;
    const int gk0   = z ? 251 : 0;

    {
        const float4* K4 = (const float4*)(g_K + ((size_t)hb*GG + gk0)*KDD);
        const float4* V4 = (const float4*)(g_V + ((size_t)hb*GG + gk0)*KDD);
        float4* Ks4 = (float4*)sm;
        float4* Vs4 = Ks4 + 251*4;
        for (int i = tid; i < nkeys*4; i += 128) {
            Ks4[i] = K4[i];
            Vs4[i] = V4[i];
        }
    }
    __syncthreads();

    const int base = blockIdx.y * 256;
    const int n0 = base + tid;
    const int n1 = base + 128 + tid;
    const bool v0 = (n0 < GG);
    const bool v1 = (n1 < GG);
    const int nn0 = v0 ? n0 : 0;
    const int nn1 = v1 ? n1 : 0;

    ull qp0[8], qp1[8], acc0[8], acc1[8];
    float l0 = 0.f, l1 = 0.f;
#pragma unroll
    for (int k = 0; k < 8; k++) { acc0[k] = 0ull; acc1[k] = 0ull; }
    loadq(g_Q + ((size_t)hb*GG + nn0)*KDD, qp0);
    loadq(g_Q + ((size_t)hb*GG + nn1)*KDD, qp1);

    // ---- base: this half's keys with Q ----
    for (int j = 0; j < nkeys; j++)
        attn_key2(KsU, VsU, j, qp0, true, l0, acc0, qp1, true, l1, acc1);

    const bool pk0 = (n0 >= 1) && (n0 <= NPP);
    const bool dl0 = (n0 >= NPP+1) && (n0 < GG);
    const bool ex0 = pk0 || dl0;
    const int  p0  = pk0 ? (n0-1) : (n0-NPP-1);
    const bool pk1 = (n1 >= 1) && (n1 <= NPP);
    const bool dl1 = (n1 >= NPP+1) && (n1 < GG);
    const bool ex1 = pk1 || dl1;
    const int  p1  = pk1 ? (n1-1) : (n1-NPP-1);

    // ---- extras: z=0 -> pick keys (local 1..250), q = pk?EQ1:EQ5
    //              z=1 -> del  keys (local 0..249), q = pk?EQ2:EQ4 ----
    {
        const float* e0src = z ? (pk0 ? g_EQ[2] : g_EQ[4]) : (pk0 ? g_EQ[1] : g_EQ[5]);
        const float* e1src = z ? (pk1 ? g_EQ[2] : g_EQ[4]) : (pk1 ? g_EQ[1] : g_EQ[5]);
        if (ex0) loadq(e0src + ((size_t)hb*NPP + p0)*KDD, qp0);
        if (ex1) loadq(e1src + ((size_t)hb*NPP + p1)*KDD, qp1);
        const int st = z ? 0 : 1;
        for (int j = st; j < st + NPP; j++)
            attn_key2(KsU, VsU, j, qp0, ex0, l0, acc0, qp1, ex1, l1, acc1);
    }

    // ---- paired extras ----
    if (z == 0) {
        // delivery query: Q_del (EQ3/W4) vs K_pick[p] = global key 1+p (local 1+p)
        if (dl0) {
            loadq(g_EQ[3] + ((size_t)hb*NPP + p0)*KDD, qp0);
            int key = 1 + p0;
            float w = ex2(dotp(qp0, KsU[key*4+0], KsU[key*4+1], KsU[key*4+2], KsU[key*4+3]));
            accum(w, acc0, l0, VsU[key*4+0], VsU[key*4+1], VsU[key*4+2], VsU[key*4+3]);
        }
        if (dl1) {
            loadq(g_EQ[3] + ((size_t)hb*NPP + p1)*KDD, qp1);
            int key = 1 + p1;
            float w = ex2(dotp(qp1, KsU[key*4+0], KsU[key*4+1], KsU[key*4+2], KsU[key*4+3]));
            accum(w, acc1, l1, VsU[key*4+0], VsU[key*4+1], VsU[key*4+2], VsU[key*4+3]);
        }
    } else {
        // pick query: Q_pick (EQ0/W1) vs K_del[p] = global key 251+p (local p)
        if (pk0) {
            loadq(g_EQ[0] + ((size_t)hb*NPP + p0)*KDD, qp0);
            int key = p0;
            float w = ex2(dotp(qp0, KsU[key*4+0], KsU[key*4+1], KsU[key*4+2], KsU[key*4+3]));
            accum(w, acc0, l0, VsU[key*4+0], VsU[key*4+1], VsU[key*4+2], VsU[key*4+3]);
        }
        if (pk1) {
            loadq(g_EQ[0] + ((size_t)hb*NPP + p1)*KDD, qp1);
            int key = p1;
            float w = ex2(dotp(qp1, KsU[key*4+0], KsU[key*4+1], KsU[key*4+2], KsU[key*4+3]));
            accum(w, acc1, l1, VsU[key*4+0], VsU[key*4+1], VsU[key*4+2], VsU[key*4+3]);
        }
    }

    // ---- store raw partials ----
    if (v0) {
        float4* o = (float4*)(g_pacc[z] + ((size_t)hb*GG + n0)*KDD);
#pragma unroll
        for (int t = 0; t < 4; t++) {
            float2 a0 = up2(acc0[2*t]);
            float2 a1 = up2(acc0[2*t+1]);
            o[t] = make_float4(a0.x, a0.y, a1.x, a1.y);
        }
        g_pl[z][(size_t)hb*GG + n0] = l0;
    }
    if (v1) {
        float4* o = (float4*)(g_pacc[z] + ((size_t)hb*GG + n1)*KDD);
#pragma unroll
        for (int t = 0; t < 4; t++) {
            float2 a0 = up2(acc1[2*t]);
            float2 a1 = up2(acc1[2*t+1]);
            o[t] = make_float4(a0.x, a0.y, a1.x, a1.y);
        }
        g_pl[z][(size_t)hb*GG + n1] = l1;
    }
}

// ---------------------------------------------------------------------------
// Kernel 3: combine partials + normalize + output projection (packed).
// out[t,e] = sum_hk heads[t,hk]*Wout[hk,e],
// heads[t, h*16+k] = (pacc0+pacc1)/(l0+l1).
// ---------------------------------------------------------------------------
__global__ void out_kernel(const float* __restrict__ Wout, float* __restrict__ out) {
    extern __shared__ float sm[];
    float* hs   = sm;                    // 32 * 132 (stride 132, float4-aligned)
    float* ws   = sm + 32*132;           // 128 * 128
    float* sinv = ws + 128*128;          // 32 * 8

    const int tid = threadIdx.x;
    const int t0  = blockIdx.x * 32;

    // ws (float4)
    {
        const float4* W4 = (const float4*)Wout;
        float4* ws4 = (float4*)ws;
        for (int i = tid; i < HH*KDD*EE/4; i += 128) ws4[i] = W4[i];
    }
    // sinv: per (token, head) reciprocal of total l
    for (int i = tid; i < 32*8; i += 128) {
        int t = i >> 3, h = i & 7;
        int tt = t0 + t;
        float l = 1.f;
        if (tt < NTOK) {
            size_t idx = (size_t)h*NTOK + tt;
            l = g_pl[0][idx] + g_pl[1][idx];
        }
        sinv[i] = 1.0f / l;
    }
    __syncthreads();

    // hs: combine partials, normalize (float4 loads/stores)
    for (int i = tid; i < 32*8*4; i += 128) {      // (t, h, k4)
        int t = i >> 5, h = (i >> 2) & 7, k4 = i & 3;
        int tt = t0 + t;
        float4 v = make_float4(0.f, 0.f, 0.f, 0.f);
        if (tt < NTOK) {
            size_t idx4 = (((size_t)h*NTOK + tt)*KDD >> 2) + k4;
            float4 a = ((const float4*)g_pacc[0])[idx4];
            float4 b = ((const float4*)g_pacc[1])[idx4];
            float s = sinv[t*8 + h];
            v = make_float4((a.x+b.x)*s, (a.y+b.y)*s, (a.z+b.z)*s, (a.w+b.w)*s);
        }
        *(float4*)(hs + t*132 + h*16 + k4*4) = v;
    }
    __syncthreads();

    const int eg = tid & 15;         // cols eg*8 .. eg*8+7
    const int tg = tid >> 4;
    const ulonglong2* wsU = (const ulonglong2*)ws;   // 32 per hk-row

    ull acc[4][4];
#pragma unroll
    for (int ti = 0; ti < 4; ti++)
#pragma unroll
        for (int c = 0; c < 4; c++) acc[ti][c] = 0ull;

#pragma unroll 4
    for (int hk = 0; hk < 128; hk++) {
        ulonglong2 wa = wsU[hk*32 + eg*2];
        ulonglong2 wb = wsU[hk*32 + eg*2 + 1];
        ull hb[4];
#pragma unroll
        for (int ti = 0; ti < 4; ti++) {
            float hv = hs[(tg*4 + ti)*132 + hk];
            hb[ti] = pk2(hv, hv);
        }
#pragma unroll
        for (int ti = 0; ti < 4; ti++) {
            fma2(acc[ti][0], hb[ti], wa.x);
            fma2(acc[ti][1], hb[ti], wa.y);
            fma2(acc[ti][2], hb[ti], wb.x);
            fma2(acc[ti][3], hb[ti], wb.y);
        }
    }

#pragma unroll
    for (int ti = 0; ti < 4; ti++) {
        int tt = t0 + tg*4 + ti;
        if (tt < NTOK) {
            float2 a0 = up2(acc[ti][0]), a1 = up2(acc[ti][1]);
            float2 a2 = up2(acc[ti][2]), a3 = up2(acc[ti][3]);
            float* o = out + (size_t)tt*EE + eg*8;
            *(float4*)(o)     = make_float4(a0.x, a0.y, a1.x, a1.y);
            *(float4*)(o + 4) = make_float4(a2.x, a2.y, a3.x, a3.y);
        }
    }
}

// ---------------------------------------------------------------------------
extern "C" void kernel_launch(void* const* d_in, const int* in_sizes, int n_in,
                              void* d_out, int out_size) {
    const float* q = (const float*)d_in[0];
    WArgs wa;
    for (int i = 0; i < 9; i++) wa.w[i] = (const float*)d_in[1 + i];
    const float* Wout = (const float*)d_in[10];
    float* out = (float*)d_out;

    const int projSmem = (64*132 + 128*64) * sizeof(float);      // 66560 B
    const int attnSmem = 251*KDD*2*sizeof(float);                // 32128 B
    const int outSmem  = (32*132 + 128*128 + 32*8) * sizeof(float);
    cudaFuncSetAttribute(proj_kernel, cudaFuncAttributeMaxDynamicSharedMemorySize, projSmem);
    cudaFuncSetAttribute(attn_kernel, cudaFuncAttributeMaxDynamicSharedMemorySize, attnSmem);
    cudaFuncSetAttribute(out_kernel,  cudaFuncAttributeMaxDynamicSharedMemorySize, outSmem);

    proj_kernel<<<dim3(756, 2), 256, projSmem>>>(q, wa);
    attn_kernel<<<dim3(HH*BB, 2, 2), 128, attnSmem>>>();
    out_kernel<<<(NTOK + 31)/32, 128, outSmem>>>(Wout, out);
}